// round 1
// baseline (speedup 1.0000x reference)
#include <cuda_runtime.h>
#include <cstdint>
#include <math.h>

#define D   128
#define N   256
#define BSZ 2
#define KNB 3
#define EPSF 1e-5f

// ---------------- scratch (no allocs allowed) ----------------
__device__ float g_P [2][BSZ][N][D];          // i-side sim projection
__device__ float g_Q [2][BSZ][N][D];          // j-side sim projection
__device__ float g_A [2][BSZ][N][D];          // absorbed features
__device__ float g_Nb[2][BSZ][N][KNB][D];     // gathered neighbor feats (ordered!)

__device__ __forceinline__ uint32_t f2tf32(float x){
    uint32_t r; asm("cvt.rna.tf32.f32 %0, %1;" : "=r"(r) : "f"(x)); return r;
}

__device__ __forceinline__ void mma8(float c[4], const uint32_t a[4],
                                     uint32_t b0, uint32_t b1){
    asm volatile(
        "mma.sync.aligned.m16n8k8.row.col.f32.tf32.tf32.f32 "
        "{%0,%1,%2,%3}, {%4,%5,%6,%7}, {%8,%9}, {%0,%1,%2,%3};\n"
        : "+f"(c[0]), "+f"(c[1]), "+f"(c[2]), "+f"(c[3])
        : "r"(a[0]), "r"(a[1]), "r"(a[2]), "r"(a[3]), "r"(b0), "r"(b1));
}

// ---------------- K1: P = f @ W0[:D], Q = f @ W0[D:] (exact fp32) ----------------
__global__ void proj_kernel(const float* __restrict__ f1, const float* __restrict__ f2,
                            const float* __restrict__ sw0){
    int gb = blockIdx.x;                 // f*512 + b*256 + i
    int f = gb >> 9, b = (gb >> 8) & 1, i = gb & 255;
    const float* feat = (f == 0 ? f1 : f2) + (b * N + i) * D;
    __shared__ float fs[D];
    int d = threadIdx.x;
    fs[d] = feat[d];
    __syncthreads();
    float p = 0.f, q = 0.f;
    #pragma unroll 8
    for (int c = 0; c < D; c++){
        float fc = fs[c];
        p = fmaf(fc, sw0[c * D + d], p);
        q = fmaf(fc, sw0[(D + c) * D + d], q);
    }
    g_P[f][b][i][d] = p;
    g_Q[f][b][i][d] = q;
}

// ---------------- K2: per-(f,b,i) sim row -> top3 (tie: lower idx) -> gather/absorb ----------------
__global__ void topk_kernel(const float* __restrict__ f1, const float* __restrict__ f2,
        const float* __restrict__ sb0, const float* __restrict__ sg,
        const float* __restrict__ sbe, const float* __restrict__ smn,
        const float* __restrict__ sv,  const float* __restrict__ sw1){
    int gb = blockIdx.x;
    int f = gb >> 9, b = (gb >> 8) & 1, i = gb & 255;
    __shared__ float Ps[D], ss[D], tt[D], w1s[D];
    __shared__ float vals[N];
    __shared__ float rv[N]; __shared__ int ri[N];
    __shared__ int bidx[KNB];
    int t = threadIdx.x;
    if (t < D){
        float s = sg[t] * rsqrtf(sv[t] + EPSF);
        ss[t]  = s;
        tt[t]  = (sb0[t] - smn[t]) * s + sbe[t];
        w1s[t] = sw1[t];
        Ps[t]  = g_P[f][b][i][t];
    }
    __syncthreads();
    // thread t == candidate j
    const float* Qrow = &g_Q[f][b][t][0];
    float sim = 0.f;
    #pragma unroll
    for (int d = 0; d < D; d += 4){
        float4 q = *(const float4*)(Qrow + d);
        float h0 = (Ps[d]   + q.x) * ss[d]   + tt[d];
        float h1 = (Ps[d+1] + q.y) * ss[d+1] + tt[d+1];
        float h2 = (Ps[d+2] + q.z) * ss[d+2] + tt[d+2];
        float h3 = (Ps[d+3] + q.w) * ss[d+3] + tt[d+3];
        sim += fmaxf(h0, 0.f) * w1s[d]   + fmaxf(h1, 0.f) * w1s[d+1]
             + fmaxf(h2, 0.f) * w1s[d+2] + fmaxf(h3, 0.f) * w1s[d+3];
    }
    if (t == i) sim = -3.402823466e38f;   // exclude self
    vals[t] = sim;
    __syncthreads();
    for (int k = 0; k < KNB; k++){
        rv[t] = vals[t]; ri[t] = t;
        __syncthreads();
        for (int s = 128; s > 0; s >>= 1){
            if (t < s){
                float v2 = rv[t + s]; int i2 = ri[t + s];
                if (v2 > rv[t] || (v2 == rv[t] && i2 < ri[t])){ rv[t] = v2; ri[t] = i2; }
            }
            __syncthreads();
        }
        int best = ri[0];
        if (t == 0) bidx[k] = best;
        if (t == best) vals[t] = -3.402823466e38f;
        __syncthreads();
    }
    const float* featb = (f == 0 ? f1 : f2) + b * N * D;
    if (t < D){
        int k0 = bidx[0], k1 = bidx[1], k2 = bidx[2];
        float n0 = featb[k0 * D + t], n1 = featb[k1 * D + t], n2 = featb[k2 * D + t];
        g_Nb[f][b][i][0][t] = n0;
        g_Nb[f][b][i][1][t] = n1;
        g_Nb[f][b][i][2][t] = n2;
        g_A[f][b][i][t] = featb[i * D + t] + 0.5f * ((n0 + n1 + n2) * (1.f / 3.f));
    }
}

// ---------------- K3: fused classifier, tf32 MMA, all 4 channels per block ----------------
// smem (floats): Xs 128*132 | Ws 128*136 | Us 16*128 | Vs 8*128 | logit 128 | ps/pt/pw1 128 each
#define SM_XS   0
#define SM_WS   16896
#define SM_US   34304
#define SM_VS   36352
#define SM_LG   37376
#define SM_PS   37504
#define SM_PT   37632
#define SM_PW1  37760
#define SMEM_FLOATS 37888

__global__ void __launch_bounds__(256, 1) cls_kernel(
    const float* __restrict__ cw0, const float* __restrict__ cb0,
    const float* __restrict__ cg,  const float* __restrict__ cbe,
    const float* __restrict__ cm,  const float* __restrict__ cv,
    const float* __restrict__ cw1, const float* __restrict__ cb1,
    float* __restrict__ out)
{
    extern __shared__ float smf[];
    uint32_t* Xs = (uint32_t*)(smf + SM_XS);
    uint32_t* Ws = (uint32_t*)(smf + SM_WS);
    float* Us    = smf + SM_US;
    float* Vs    = smf + SM_VS;
    float* logit = smf + SM_LG;
    float* ps    = smf + SM_PS;
    float* pt    = smf + SM_PT;
    float* pw1   = smf + SM_PW1;

    int t = threadIdx.x;
    int b = blockIdx.z, i0 = blockIdx.y * 16, j0 = blockIdx.x * 8;

    // stage W0 once (tf32), conflict-free stride 136
    for (int e = t; e < D * D; e += 256){
        int k = e >> 7, d = e & 127;
        Ws[k * 136 + d] = f2tf32(cw0[e]);
    }
    if (t < D){
        float s = cg[t] * rsqrtf(cv[t] + EPSF);
        ps[t]  = s;
        pt[t]  = (cb0[t] - cm[t]) * s + cbe[t];
        pw1[t] = cw1[t];
    }
    float b1v = cb1[0];
    float accPair = 0.f;

    int lane = t & 31, warp = t >> 5;
    int gid = lane >> 2, tig = lane & 3;
    int warp_m = warp & 3, warp_n = warp >> 2;
    int rm = warp_m * 32;

    for (int ch = 0; ch < 4; ch++){
        const float* Ubase; const float* Vbase; int rstride;
        if (ch == 0){ Ubase = &g_A[0][b][0][0];         Vbase = &g_A[1][b][0][0];         rstride = D; }
        else        { Ubase = &g_Nb[0][b][0][ch-1][0];  Vbase = &g_Nb[1][b][0][ch-1][0];  rstride = KNB * D; }
        __syncthreads();                               // protect smem reuse from prev channel
        for (int e = t; e < 16 * D; e += 256){
            int r = e >> 7, c = e & 127;
            Us[e] = Ubase[(i0 + r) * rstride + c];
        }
        for (int e = t; e < 8 * D; e += 256){
            int r = e >> 7, c = e & 127;
            Vs[e] = Vbase[(j0 + r) * rstride + c];
        }
        if (t < 128) logit[t] = b1v;
        __syncthreads();
        // build X = |U_i - V_j| tile (128 pairs x 128), tf32, stride 132
        for (int e = t; e < 128 * 128; e += 256){
            int row = e >> 7, c = e & 127;
            Xs[row * 132 + c] = f2tf32(fabsf(Us[(row >> 3) * 128 + c] - Vs[(row & 7) * 128 + c]));
        }
        __syncthreads();

        float cacc[2][8][4];
        #pragma unroll
        for (int mt = 0; mt < 2; mt++)
            #pragma unroll
            for (int nt = 0; nt < 8; nt++)
                #pragma unroll
                for (int q = 0; q < 4; q++) cacc[mt][nt][q] = 0.f;

        #pragma unroll 1
        for (int k0 = 0; k0 < 128; k0 += 8){
            uint32_t a[2][4];
            #pragma unroll
            for (int mt = 0; mt < 2; mt++){
                int r0 = rm + mt * 16 + gid;
                a[mt][0] = Xs[ r0      * 132 + k0 + tig];
                a[mt][1] = Xs[(r0 + 8) * 132 + k0 + tig];
                a[mt][2] = Xs[ r0      * 132 + k0 + tig + 4];
                a[mt][3] = Xs[(r0 + 8) * 132 + k0 + tig + 4];
            }
            #pragma unroll
            for (int nt = 0; nt < 8; nt++){
                int dbase = warp_n * 64 + nt * 8 + gid;
                uint32_t bb0 = Ws[(k0 + tig)     * 136 + dbase];
                uint32_t bb1 = Ws[(k0 + tig + 4) * 136 + dbase];
                mma8(cacc[0][nt], a[0], bb0, bb1);
                mma8(cacc[1][nt], a[1], bb0, bb1);
            }
        }

        // epilogue: BN fold + ReLU + w1-dot, reduce d within warp then across N-warps
        float part[4] = {0.f, 0.f, 0.f, 0.f};
        #pragma unroll
        for (int mt = 0; mt < 2; mt++){
            #pragma unroll
            for (int nt = 0; nt < 8; nt++){
                int d0 = warp_n * 64 + nt * 8 + 2 * tig;
                float e0 = fmaxf(cacc[mt][nt][0] * ps[d0]     + pt[d0],     0.f) * pw1[d0];
                float e1 = fmaxf(cacc[mt][nt][1] * ps[d0 + 1] + pt[d0 + 1], 0.f) * pw1[d0 + 1];
                float e2 = fmaxf(cacc[mt][nt][2] * ps[d0]     + pt[d0],     0.f) * pw1[d0];
                float e3 = fmaxf(cacc[mt][nt][3] * ps[d0 + 1] + pt[d0 + 1], 0.f) * pw1[d0 + 1];
                part[mt * 2]     += e0 + e1;
                part[mt * 2 + 1] += e2 + e3;
            }
        }
        #pragma unroll
        for (int p = 0; p < 4; p++){
            part[p] += __shfl_xor_sync(0xffffffffu, part[p], 1);
            part[p] += __shfl_xor_sync(0xffffffffu, part[p], 2);
        }
        if (tig == 0){
            atomicAdd(&logit[rm + gid],          part[0]);
            atomicAdd(&logit[rm + gid + 8],      part[1]);
            atomicAdd(&logit[rm + 16 + gid],     part[2]);
            atomicAdd(&logit[rm + 16 + gid + 8], part[3]);
        }
        __syncthreads();
        if (t < 128){
            float sc = 1.f / (1.f + expf(-logit[t]));
            accPair += (ch == 0 ? 0.5f : (1.f / 6.f)) * sc;
        }
    }
    if (t < 128){
        int il = t >> 3, jl = t & 7;
        out[(b * N + i0 + il) * N + (j0 + jl)] = accPair;
    }
}

// ---------------- launch ----------------
extern "C" void kernel_launch(void* const* d_in, const int* in_sizes, int n_in,
                              void* d_out, int out_size){
    const float* f1  = (const float*)d_in[0];
    const float* f2  = (const float*)d_in[1];
    const float* sw0 = (const float*)d_in[2];
    const float* sb0 = (const float*)d_in[3];
    const float* sg  = (const float*)d_in[4];
    const float* sbe = (const float*)d_in[5];
    const float* smn = (const float*)d_in[6];
    const float* sv  = (const float*)d_in[7];
    const float* sw1 = (const float*)d_in[8];
    /* d_in[9] = sim_b1: rank-invariant, unused */
    const float* cw0 = (const float*)d_in[10];
    const float* cb0 = (const float*)d_in[11];
    const float* cg  = (const float*)d_in[12];
    const float* cbe = (const float*)d_in[13];
    const float* cm  = (const float*)d_in[14];
    const float* cv  = (const float*)d_in[15];
    const float* cw1 = (const float*)d_in[16];
    const float* cb1 = (const float*)d_in[17];
    float* out = (float*)d_out;

    cudaFuncSetAttribute(cls_kernel, cudaFuncAttributeMaxDynamicSharedMemorySize,
                         SMEM_FLOATS * (int)sizeof(float));

    proj_kernel<<<1024, 128>>>(f1, f2, sw0);
    topk_kernel<<<1024, 256>>>(f1, f2, sb0, sg, sbe, smn, sv, sw1);
    dim3 grid(32, 16, 2);
    cls_kernel<<<grid, 256, SMEM_FLOATS * (int)sizeof(float)>>>(
        cw0, cb0, cg, cbe, cm, cv, cw1, cb1, out);
}

// round 2
// speedup vs baseline: 1.0059x; 1.0059x over previous
#include <cuda_runtime.h>
#include <cstdint>
#include <math.h>

#define D   128
#define N   256
#define BSZ 2
#define KNB 3
#define EPSF 1e-5f

// ---------------- scratch (no allocs allowed) ----------------
__device__ float g_P [2][BSZ][N][D];          // i-side sim projection
__device__ float g_Q [2][BSZ][N][D];          // j-side sim projection
__device__ float g_A [2][BSZ][N][D];          // absorbed features
__device__ float g_Nb[2][BSZ][N][KNB][D];     // gathered neighbor feats (ordered!)

__device__ __forceinline__ uint32_t f2tf32(float x){
    uint32_t r; asm("cvt.rna.tf32.f32 %0, %1;" : "=r"(r) : "f"(x)); return r;
}

__device__ __forceinline__ void mma8(float c[4], const uint32_t a[4],
                                     uint32_t b0, uint32_t b1){
    asm volatile(
        "mma.sync.aligned.m16n8k8.row.col.f32.tf32.tf32.f32 "
        "{%0,%1,%2,%3}, {%4,%5,%6,%7}, {%8,%9}, {%0,%1,%2,%3};\n"
        : "+f"(c[0]), "+f"(c[1]), "+f"(c[2]), "+f"(c[3])
        : "r"(a[0]), "r"(a[1]), "r"(a[2]), "r"(a[3]), "r"(b0), "r"(b1));
}

// ---------------- K1: P = f @ W0[:D], Q = f @ W0[D:] (exact fp32) ----------------
__global__ void proj_kernel(const float* __restrict__ f1, const float* __restrict__ f2,
                            const float* __restrict__ sw0){
    int gb = blockIdx.x;                 // f*512 + b*256 + i
    int f = gb >> 9, b = (gb >> 8) & 1, i = gb & 255;
    const float* feat = (f == 0 ? f1 : f2) + (b * N + i) * D;
    __shared__ float fs[D];
    int d = threadIdx.x;
    fs[d] = feat[d];
    __syncthreads();
    float p = 0.f, q = 0.f;
    #pragma unroll 8
    for (int c = 0; c < D; c++){
        float fc = fs[c];
        p = fmaf(fc, sw0[c * D + d], p);
        q = fmaf(fc, sw0[(D + c) * D + d], q);
    }
    g_P[f][b][i][d] = p;
    g_Q[f][b][i][d] = q;
}

// ---------------- K2: per-(f,b,i) sim row -> top3 (tie: lower idx) -> gather/absorb ----------------
__global__ void topk_kernel(const float* __restrict__ f1, const float* __restrict__ f2,
        const float* __restrict__ sb0, const float* __restrict__ sg,
        const float* __restrict__ sbe, const float* __restrict__ smn,
        const float* __restrict__ sv,  const float* __restrict__ sw1){
    int gb = blockIdx.x;
    int f = gb >> 9, b = (gb >> 8) & 1, i = gb & 255;
    __shared__ float Ps[D], ss[D], tt[D], w1s[D];
    __shared__ float vals[N];
    __shared__ float rv[N]; __shared__ int ri[N];
    __shared__ int bidx[KNB];
    int t = threadIdx.x;
    if (t < D){
        float s = sg[t] * rsqrtf(sv[t] + EPSF);
        ss[t]  = s;
        tt[t]  = (sb0[t] - smn[t]) * s + sbe[t];
        w1s[t] = sw1[t];
        Ps[t]  = g_P[f][b][i][t];
    }
    __syncthreads();
    // thread t == candidate j
    const float* Qrow = &g_Q[f][b][t][0];
    float sim = 0.f;
    #pragma unroll
    for (int d = 0; d < D; d += 4){
        float4 q = *(const float4*)(Qrow + d);
        float h0 = (Ps[d]   + q.x) * ss[d]   + tt[d];
        float h1 = (Ps[d+1] + q.y) * ss[d+1] + tt[d+1];
        float h2 = (Ps[d+2] + q.z) * ss[d+2] + tt[d+2];
        float h3 = (Ps[d+3] + q.w) * ss[d+3] + tt[d+3];
        sim += fmaxf(h0, 0.f) * w1s[d]   + fmaxf(h1, 0.f) * w1s[d+1]
             + fmaxf(h2, 0.f) * w1s[d+2] + fmaxf(h3, 0.f) * w1s[d+3];
    }
    if (t == i) sim = -3.402823466e38f;   // exclude self
    vals[t] = sim;
    __syncthreads();
    for (int k = 0; k < KNB; k++){
        rv[t] = vals[t]; ri[t] = t;
        __syncthreads();
        for (int s = 128; s > 0; s >>= 1){
            if (t < s){
                float v2 = rv[t + s]; int i2 = ri[t + s];
                if (v2 > rv[t] || (v2 == rv[t] && i2 < ri[t])){ rv[t] = v2; ri[t] = i2; }
            }
            __syncthreads();
        }
        int best = ri[0];
        if (t == 0) bidx[k] = best;
        if (t == best) vals[t] = -3.402823466e38f;
        __syncthreads();
    }
    const float* featb = (f == 0 ? f1 : f2) + b * N * D;
    if (t < D){
        int k0 = bidx[0], k1 = bidx[1], k2 = bidx[2];
        float n0 = featb[k0 * D + t], n1 = featb[k1 * D + t], n2 = featb[k2 * D + t];
        g_Nb[f][b][i][0][t] = n0;
        g_Nb[f][b][i][1][t] = n1;
        g_Nb[f][b][i][2][t] = n2;
        g_A[f][b][i][t] = featb[i * D + t] + 0.5f * ((n0 + n1 + n2) * (1.f / 3.f));
    }
}

// ---------------- K3: fused classifier, tf32 MMA, all 4 channels per block ----------------
// smem (floats): Xs 128*132 | Ws 128*136 | Us 16*128 | Vs 8*128 | logit 128 | ps/pt/pw1 128 each
#define SM_XS   0
#define SM_WS   16896
#define SM_US   34304
#define SM_VS   36352
#define SM_LG   37376
#define SM_PS   37504
#define SM_PT   37632
#define SM_PW1  37760
#define SMEM_FLOATS 37888

__global__ void __launch_bounds__(256, 1) cls_kernel(
    const float* __restrict__ cw0, const float* __restrict__ cb0,
    const float* __restrict__ cg,  const float* __restrict__ cbe,
    const float* __restrict__ cm,  const float* __restrict__ cv,
    const float* __restrict__ cw1, const float* __restrict__ cb1,
    float* __restrict__ out)
{
    extern __shared__ float smf[];
    uint32_t* Xs = (uint32_t*)(smf + SM_XS);
    uint32_t* Ws = (uint32_t*)(smf + SM_WS);
    float* Us    = smf + SM_US;
    float* Vs    = smf + SM_VS;
    float* logit = smf + SM_LG;
    float* ps    = smf + SM_PS;
    float* pt    = smf + SM_PT;
    float* pw1   = smf + SM_PW1;

    int t = threadIdx.x;
    int b = blockIdx.z, i0 = blockIdx.y * 16, j0 = blockIdx.x * 8;

    // stage W0 once (tf32), conflict-free stride 136
    for (int e = t; e < D * D; e += 256){
        int k = e >> 7, d = e & 127;
        Ws[k * 136 + d] = f2tf32(cw0[e]);
    }
    if (t < D){
        float s = cg[t] * rsqrtf(cv[t] + EPSF);
        ps[t]  = s;
        pt[t]  = (cb0[t] - cm[t]) * s + cbe[t];
        pw1[t] = cw1[t];
    }
    float b1v = cb1[0];
    float accPair = 0.f;

    int lane = t & 31, warp = t >> 5;
    int gid = lane >> 2, tig = lane & 3;
    int warp_m = warp & 3, warp_n = warp >> 2;
    int rm = warp_m * 32;

    for (int ch = 0; ch < 4; ch++){
        const float* Ubase; const float* Vbase; int rstride;
        if (ch == 0){ Ubase = &g_A[0][b][0][0];         Vbase = &g_A[1][b][0][0];         rstride = D; }
        else        { Ubase = &g_Nb[0][b][0][ch-1][0];  Vbase = &g_Nb[1][b][0][ch-1][0];  rstride = KNB * D; }
        __syncthreads();                               // protect smem reuse from prev channel
        for (int e = t; e < 16 * D; e += 256){
            int r = e >> 7, c = e & 127;
            Us[e] = Ubase[(i0 + r) * rstride + c];
        }
        for (int e = t; e < 8 * D; e += 256){
            int r = e >> 7, c = e & 127;
            Vs[e] = Vbase[(j0 + r) * rstride + c];
        }
        if (t < 128) logit[t] = b1v;
        __syncthreads();
        // build X = |U_i - V_j| tile (128 pairs x 128), tf32, stride 132
        for (int e = t; e < 128 * 128; e += 256){
            int row = e >> 7, c = e & 127;
            Xs[row * 132 + c] = f2tf32(fabsf(Us[(row >> 3) * 128 + c] - Vs[(row & 7) * 128 + c]));
        }
        __syncthreads();

        float cacc[2][8][4];
        #pragma unroll
        for (int mt = 0; mt < 2; mt++)
            #pragma unroll
            for (int nt = 0; nt < 8; nt++)
                #pragma unroll
                for (int q = 0; q < 4; q++) cacc[mt][nt][q] = 0.f;

        #pragma unroll 1
        for (int k0 = 0; k0 < 128; k0 += 8){
            uint32_t a[2][4];
            #pragma unroll
            for (int mt = 0; mt < 2; mt++){
                int r0 = rm + mt * 16 + gid;
                a[mt][0] = Xs[ r0      * 132 + k0 + tig];
                a[mt][1] = Xs[(r0 + 8) * 132 + k0 + tig];
                a[mt][2] = Xs[ r0      * 132 + k0 + tig + 4];
                a[mt][3] = Xs[(r0 + 8) * 132 + k0 + tig + 4];
            }
            #pragma unroll
            for (int nt = 0; nt < 8; nt++){
                int dbase = warp_n * 64 + nt * 8 + gid;
                uint32_t bb0 = Ws[(k0 + tig)     * 136 + dbase];
                uint32_t bb1 = Ws[(k0 + tig + 4) * 136 + dbase];
                mma8(cacc[0][nt], a[0], bb0, bb1);
                mma8(cacc[1][nt], a[1], bb0, bb1);
            }
        }

        // epilogue: BN fold + ReLU + w1-dot, reduce d within warp then across N-warps
        float part[4] = {0.f, 0.f, 0.f, 0.f};
        #pragma unroll
        for (int mt = 0; mt < 2; mt++){
            #pragma unroll
            for (int nt = 0; nt < 8; nt++){
                int d0 = warp_n * 64 + nt * 8 + 2 * tig;
                float e0 = fmaxf(cacc[mt][nt][0] * ps[d0]     + pt[d0],     0.f) * pw1[d0];
                float e1 = fmaxf(cacc[mt][nt][1] * ps[d0 + 1] + pt[d0 + 1], 0.f) * pw1[d0 + 1];
                float e2 = fmaxf(cacc[mt][nt][2] * ps[d0]     + pt[d0],     0.f) * pw1[d0];
                float e3 = fmaxf(cacc[mt][nt][3] * ps[d0 + 1] + pt[d0 + 1], 0.f) * pw1[d0 + 1];
                part[mt * 2]     += e0 + e1;
                part[mt * 2 + 1] += e2 + e3;
            }
        }
        #pragma unroll
        for (int p = 0; p < 4; p++){
            part[p] += __shfl_xor_sync(0xffffffffu, part[p], 1);
            part[p] += __shfl_xor_sync(0xffffffffu, part[p], 2);
        }
        if (tig == 0){
            atomicAdd(&logit[rm + gid],          part[0]);
            atomicAdd(&logit[rm + gid + 8],      part[1]);
            atomicAdd(&logit[rm + 16 + gid],     part[2]);
            atomicAdd(&logit[rm + 16 + gid + 8], part[3]);
        }
        __syncthreads();
        if (t < 128){
            float sc = 1.f / (1.f + expf(-logit[t]));
            accPair += (ch == 0 ? 0.5f : (1.f / 6.f)) * sc;
        }
    }
    if (t < 128){
        int il = t >> 3, jl = t & 7;
        out[(b * N + i0 + il) * N + (j0 + jl)] = accPair;
    }
}

// ---------------- launch ----------------
extern "C" void kernel_launch(void* const* d_in, const int* in_sizes, int n_in,
                              void* d_out, int out_size){
    const float* f1  = (const float*)d_in[0];
    const float* f2  = (const float*)d_in[1];
    const float* sw0 = (const float*)d_in[2];
    const float* sb0 = (const float*)d_in[3];
    const float* sg  = (const float*)d_in[4];
    const float* sbe = (const float*)d_in[5];
    const float* smn = (const float*)d_in[6];
    const float* sv  = (const float*)d_in[7];
    const float* sw1 = (const float*)d_in[8];
    /* d_in[9] = sim_b1: rank-invariant, unused */
    const float* cw0 = (const float*)d_in[10];
    const float* cb0 = (const float*)d_in[11];
    const float* cg  = (const float*)d_in[12];
    const float* cbe = (const float*)d_in[13];
    const float* cm  = (const float*)d_in[14];
    const float* cv  = (const float*)d_in[15];
    const float* cw1 = (const float*)d_in[16];
    const float* cb1 = (const float*)d_in[17];
    float* out = (float*)d_out;

    cudaFuncSetAttribute(cls_kernel, cudaFuncAttributeMaxDynamicSharedMemorySize,
                         SMEM_FLOATS * (int)sizeof(float));

    proj_kernel<<<1024, 128>>>(f1, f2, sw0);
    topk_kernel<<<1024, 256>>>(f1, f2, sb0, sg, sbe, smn, sv, sw1);
    dim3 grid(32, 16, 2);
    cls_kernel<<<grid, 256, SMEM_FLOATS * (int)sizeof(float)>>>(
        cw0, cb0, cg, cbe, cm, cv, cw1, cb1, out);
}

// round 3
// speedup vs baseline: 1.6029x; 1.5935x over previous
#include <cuda_runtime.h>
#include <cuda_fp16.h>
#include <cstdint>
#include <math.h>

#define D   128
#define N   256
#define BSZ 2
#define KNB 3
#define EPSF 1e-5f
#define NEG_INF (-3.402823466e38f)

// ---------------- scratch (no allocs allowed) ----------------
__device__ float g_P [2][BSZ][N][D];          // i-side sim projection
__device__ float g_Q [2][BSZ][N][D];          // j-side sim projection
__device__ float g_A [2][BSZ][N][D];          // absorbed features
__device__ float g_Nb[2][BSZ][N][KNB][D];     // gathered neighbor feats (ordered!)

// ---------------- MMA / LDSM helpers (fp16, m16n8k16) ----------------
__device__ __forceinline__ void mma16(float c[4], const uint32_t a[4],
                                      uint32_t b0, uint32_t b1){
    asm volatile(
        "mma.sync.aligned.m16n8k16.row.col.f32.f16.f16.f32 "
        "{%0,%1,%2,%3}, {%4,%5,%6,%7}, {%8,%9}, {%0,%1,%2,%3};\n"
        : "+f"(c[0]), "+f"(c[1]), "+f"(c[2]), "+f"(c[3])
        : "r"(a[0]), "r"(a[1]), "r"(a[2]), "r"(a[3]), "r"(b0), "r"(b1));
}

__device__ __forceinline__ void ldm4(uint32_t r[4], uint32_t addr){
    asm volatile("ldmatrix.sync.aligned.m8n8.x4.shared.b16 {%0,%1,%2,%3}, [%4];"
        : "=r"(r[0]), "=r"(r[1]), "=r"(r[2]), "=r"(r[3]) : "r"(addr));
}

// ---------------- K1: P = f @ W0[:D], Q = f @ W0[D:]  (exact fp32) ----------------
// 128 blocks x 256 threads, 8 rows per block -> sw0 L2 traffic 17MB instead of 134MB
__global__ void proj_kernel(const float* __restrict__ f1, const float* __restrict__ f2,
                            const float* __restrict__ sw0){
    __shared__ float fs[8][D];
    int r0 = blockIdx.x * 8;                  // global row id: f*512 + b*256 + i
    int f = r0 >> 9, b = (r0 >> 8) & 1, i0 = r0 & 255;
    const float* featb = (f == 0 ? f1 : f2) + b * N * D;
    int t = threadIdx.x;
    int d = t & 127, which = t >> 7;          // which: 0 -> P, 1 -> Q
    for (int e = t; e < 8 * D; e += 256){
        int r = e >> 7, c = e & 127;
        fs[r][c] = featb[(i0 + r) * D + c];
    }
    __syncthreads();
    float acc[8] = {0,0,0,0,0,0,0,0};
    const float* wbase = sw0 + which * D * D + d;
    #pragma unroll 4
    for (int c = 0; c < D; c++){
        float w = wbase[c * D];
        #pragma unroll
        for (int r = 0; r < 8; r++) acc[r] = fmaf(fs[r][c], w, acc[r]);
    }
    float* dst = which ? &g_Q[f][b][0][0] : &g_P[f][b][0][0];
    #pragma unroll
    for (int r = 0; r < 8; r++) dst[(i0 + r) * D + d] = acc[r];
}

// ---------------- K2: per-(f,b,i) sim row -> top3 (tie: lower idx) -> gather/absorb ----------------
__global__ void topk_kernel(const float* __restrict__ f1, const float* __restrict__ f2,
        const float* __restrict__ sb0, const float* __restrict__ sg,
        const float* __restrict__ sbe, const float* __restrict__ smn,
        const float* __restrict__ sv,  const float* __restrict__ sw1){
    int gb = blockIdx.x;
    int f = gb >> 9, b = (gb >> 8) & 1, i = gb & 255;
    __shared__ float Ps[D], ss[D], tt[D], w1s[D];
    __shared__ float wv[8]; __shared__ int wi[8];
    __shared__ int bidx[KNB];
    int t = threadIdx.x, lane = t & 31, warp = t >> 5;
    if (t < D){
        float s = sg[t] * rsqrtf(sv[t] + EPSF);
        ss[t]  = s;
        tt[t]  = (sb0[t] - smn[t]) * s + sbe[t];
        w1s[t] = sw1[t];
        Ps[t]  = g_P[f][b][i][t];
    }
    __syncthreads();
    // thread t == candidate j (exact fp32 sim -> ranking identical to reference fp32)
    const float* Qrow = &g_Q[f][b][t][0];
    float simv = 0.f;
    #pragma unroll
    for (int d = 0; d < D; d += 4){
        float4 q = *(const float4*)(Qrow + d);
        float h0 = (Ps[d]   + q.x) * ss[d]   + tt[d];
        float h1 = (Ps[d+1] + q.y) * ss[d+1] + tt[d+1];
        float h2 = (Ps[d+2] + q.z) * ss[d+2] + tt[d+2];
        float h3 = (Ps[d+3] + q.w) * ss[d+3] + tt[d+3];
        simv += fmaxf(h0, 0.f) * w1s[d]   + fmaxf(h1, 0.f) * w1s[d+1]
              + fmaxf(h2, 0.f) * w1s[d+2] + fmaxf(h3, 0.f) * w1s[d+3];
    }
    if (t == i) simv = NEG_INF;               // exclude self
    for (int k = 0; k < KNB; k++){
        float v = simv; int idx = t;
        #pragma unroll
        for (int off = 16; off; off >>= 1){
            float ov = __shfl_down_sync(0xffffffffu, v, off);
            int   oi = __shfl_down_sync(0xffffffffu, idx, off);
            if (ov > v || (ov == v && oi < idx)){ v = ov; idx = oi; }
        }
        if (lane == 0){ wv[warp] = v; wi[warp] = idx; }
        __syncthreads();
        if (warp == 0){
            float v2 = (lane < 8) ? wv[lane] : NEG_INF;
            int   i2 = (lane < 8) ? wi[lane] : 0x7fffffff;
            #pragma unroll
            for (int off = 4; off; off >>= 1){
                float ov = __shfl_down_sync(0xffffffffu, v2, off);
                int   oi = __shfl_down_sync(0xffffffffu, i2, off);
                if (ov > v2 || (ov == v2 && oi < i2)){ v2 = ov; i2 = oi; }
            }
            if (lane == 0) bidx[k] = i2;
        }
        __syncthreads();
        if (t == bidx[k]) simv = NEG_INF;     // invalidate winner for next pass
    }
    const float* featb = (f == 0 ? f1 : f2) + b * N * D;
    if (t < D){
        int k0 = bidx[0], k1 = bidx[1], k2 = bidx[2];
        float n0 = featb[k0 * D + t], n1 = featb[k1 * D + t], n2 = featb[k2 * D + t];
        g_Nb[f][b][i][0][t] = n0;
        g_Nb[f][b][i][1][t] = n1;
        g_Nb[f][b][i][2][t] = n2;
        g_A[f][b][i][t] = featb[i * D + t] + 0.5f * ((n0 + n1 + n2) * (1.f / 3.f));
    }
}

// ---------------- K3: fused classifier, fp16 MMA + ldmatrix, 2 blocks/SM ----------------
// smem bytes:
//   Wt (half) [128 d][136 kpad]  34816    A operand: Wt[d][k] = W[k][d]
//   Xs (half) [128 pair][136]    34816    B operand: Xs[pair][k] = |U-V| (fp16)
//   Us (f32)  16*128              8192
//   Vs (f32)   8*128              4096
//   logit     128                  512
//   ps/pt/pw1 128 each            1536
#define OFF_WT 0
#define OFF_XS 34816
#define OFF_US 69632
#define OFF_VS 77824
#define OFF_LG 81920
#define OFF_PS 82432
#define OFF_PT 82944
#define OFF_PW 83456
#define SMEM_BYTES 83968
#define KPAD 136

__global__ void __launch_bounds__(256, 2) cls_kernel(
    const float* __restrict__ cw0, const float* __restrict__ cb0,
    const float* __restrict__ cg,  const float* __restrict__ cbe,
    const float* __restrict__ cm,  const float* __restrict__ cv,
    const float* __restrict__ cw1, const float* __restrict__ cb1,
    float* __restrict__ out)
{
    extern __shared__ char smb[];
    half*  Wt    = (half*) (smb + OFF_WT);
    half*  Xs    = (half*) (smb + OFF_XS);
    float* Us    = (float*)(smb + OFF_US);
    float* Vs    = (float*)(smb + OFF_VS);
    float* logit = (float*)(smb + OFF_LG);
    float* ps    = (float*)(smb + OFF_PS);
    float* pt    = (float*)(smb + OFF_PT);
    float* pw1   = (float*)(smb + OFF_PW);
    uint32_t wt_s = (uint32_t)__cvta_generic_to_shared(Wt);
    uint32_t xs_s = (uint32_t)__cvta_generic_to_shared(Xs);

    int t = threadIdx.x;
    int b = blockIdx.z, i0 = blockIdx.y * 16, j0 = blockIdx.x * 8;
    int lane = t & 31, warp = t >> 5;
    int gid = lane >> 2, tig = lane & 3;
    int warp_m = warp & 3, warp_n = warp >> 2;     // m = d_out (4 warps x 32), n = pair (2 warps x 64)

    // stage Wt[d][k] = cw0[k*D+d] as fp16 (one-time per block; coalesced global read)
    for (int e = t; e < D * D; e += 256){
        int k = e >> 7, d = e & 127;
        Wt[d * KPAD + k] = __float2half_rn(cw0[e]);
    }
    if (t < D){
        float s = cg[t] * rsqrtf(cv[t] + EPSF);
        ps[t]  = s;
        pt[t]  = (cb0[t] - cm[t]) * s + cbe[t];
        pw1[t] = cw1[t];
    }
    float b1v = cb1[0];
    float accPair = 0.f;

    // A (Wt) ldmatrix address: row = warp_m*32 + mt*16 + (lane&15), col = k0 + (lane>>4)*8
    int a_row_base = warp_m * 32 + (lane & 15);
    int a_col_off  = (lane >> 4) << 3;
    // B (Xs) ldmatrix address: row = n0 + (lane&7) + ((lane>>4)&1)*8, col = k0 + ((lane>>3)&1)*8
    int b_row_off = (lane & 7) + (((lane >> 4) & 1) << 3);
    int b_col_off = ((lane >> 3) & 1) << 3;

    for (int ch = 0; ch < 4; ch++){
        const float* Ubase; const float* Vbase; int rstride;
        if (ch == 0){ Ubase = &g_A[0][b][0][0];          Vbase = &g_A[1][b][0][0];          rstride = D; }
        else        { Ubase = &g_Nb[0][b][0][ch-1][0];   Vbase = &g_Nb[1][b][0][ch-1][0];   rstride = KNB * D; }
        __syncthreads();                                 // smem reuse safe vs prev channel
        for (int e = t; e < 16 * D; e += 256){
            int r = e >> 7, c = e & 127;
            Us[e] = Ubase[(i0 + r) * rstride + c];
        }
        for (int e = t; e < 8 * D; e += 256){
            int r = e >> 7, c = e & 127;
            Vs[e] = Vbase[(j0 + r) * rstride + c];
        }
        if (t < 128) logit[t] = b1v;
        __syncthreads();
        // build X = |U_il - V_jl| as fp16, row-major [pair][k], pair = il*8 + jl
        for (int e = t; e < 128 * 64; e += 256){
            int pair = e >> 6, kp = (e & 63) << 1;
            const float* ur = Us + (pair >> 3) * D + kp;
            const float* vr = Vs + (pair & 7) * D + kp;
            half2 h = __floats2half2_rn(fabsf(ur[0] - vr[0]), fabsf(ur[1] - vr[1]));
            *(half2*)(Xs + pair * KPAD + kp) = h;
        }
        __syncthreads();

        float cacc[2][8][4];
        #pragma unroll
        for (int mt = 0; mt < 2; mt++)
            #pragma unroll
            for (int nt = 0; nt < 8; nt++)
                #pragma unroll
                for (int q = 0; q < 4; q++) cacc[mt][nt][q] = 0.f;

        #pragma unroll 1
        for (int ks = 0; ks < 8; ks++){
            int k0 = ks * 16;
            uint32_t aW[2][4];
            #pragma unroll
            for (int mt = 0; mt < 2; mt++){
                uint32_t addr = wt_s + ((a_row_base + mt * 16) * KPAD + k0 + a_col_off) * 2;
                ldm4(aW[mt], addr);
            }
            #pragma unroll
            for (int ntp = 0; ntp < 4; ntp++){
                int n0 = warp_n * 64 + ntp * 16;
                uint32_t bX[4];
                uint32_t addr = xs_s + ((n0 + b_row_off) * KPAD + k0 + b_col_off) * 2;
                ldm4(bX, addr);
                mma16(cacc[0][ntp * 2],     aW[0], bX[0], bX[1]);
                mma16(cacc[1][ntp * 2],     aW[1], bX[0], bX[1]);
                mma16(cacc[0][ntp * 2 + 1], aW[0], bX[2], bX[3]);
                mma16(cacc[1][ntp * 2 + 1], aW[1], bX[2], bX[3]);
            }
        }

        // epilogue: acc holds h[d][pair]; fold BN+ReLU+w1 and reduce over d
        float part0[8], part1[8];
        #pragma unroll
        for (int nt = 0; nt < 8; nt++){ part0[nt] = 0.f; part1[nt] = 0.f; }
        #pragma unroll
        for (int mt = 0; mt < 2; mt++){
            int d0 = warp_m * 32 + mt * 16 + gid, d1 = d0 + 8;
            float s0 = ps[d0], t0 = pt[d0], w0 = pw1[d0];
            float s1 = ps[d1], t1 = pt[d1], w1 = pw1[d1];
            #pragma unroll
            for (int nt = 0; nt < 8; nt++){
                float* c = cacc[mt][nt];
                part0[nt] += fmaxf(c[0] * s0 + t0, 0.f) * w0 + fmaxf(c[2] * s1 + t1, 0.f) * w1;
                part1[nt] += fmaxf(c[1] * s0 + t0, 0.f) * w0 + fmaxf(c[3] * s1 + t1, 0.f) * w1;
            }
        }
        #pragma unroll
        for (int nt = 0; nt < 8; nt++){
            #pragma unroll
            for (int off = 4; off <= 16; off <<= 1){
                part0[nt] += __shfl_xor_sync(0xffffffffu, part0[nt], off);
                part1[nt] += __shfl_xor_sync(0xffffffffu, part1[nt], off);
            }
        }
        if (gid == 0){
            #pragma unroll
            for (int nt = 0; nt < 8; nt++){
                int p = warp_n * 64 + nt * 8 + 2 * tig;
                atomicAdd(&logit[p],     part0[nt]);
                atomicAdd(&logit[p + 1], part1[nt]);
            }
        }
        __syncthreads();
        if (t < 128){
            float sc = 1.f / (1.f + expf(-logit[t]));
            accPair += (ch == 0 ? 0.5f : (1.f / 6.f)) * sc;
        }
    }
    if (t < 128){
        int il = t >> 3, jl = t & 7;
        out[(b * N + i0 + il) * N + (j0 + jl)] = accPair;
    }
}

// ---------------- launch ----------------
extern "C" void kernel_launch(void* const* d_in, const int* in_sizes, int n_in,
                              void* d_out, int out_size){
    const float* f1  = (const float*)d_in[0];
    const float* f2  = (const float*)d_in[1];
    const float* sw0 = (const float*)d_in[2];
    const float* sb0 = (const float*)d_in[3];
    const float* sg  = (const float*)d_in[4];
    const float* sbe = (const float*)d_in[5];
    const float* smn = (const float*)d_in[6];
    const float* sv  = (const float*)d_in[7];
    const float* sw1 = (const float*)d_in[8];
    /* d_in[9] = sim_b1: rank-invariant, unused */
    const float* cw0 = (const float*)d_in[10];
    const float* cb0 = (const float*)d_in[11];
    const float* cg  = (const float*)d_in[12];
    const float* cbe = (const float*)d_in[13];
    const float* cm  = (const float*)d_in[14];
    const float* cv  = (const float*)d_in[15];
    const float* cw1 = (const float*)d_in[16];
    const float* cb1 = (const float*)d_in[17];
    float* out = (float*)d_out;

    cudaFuncSetAttribute(cls_kernel, cudaFuncAttributeMaxDynamicSharedMemorySize,
                         SMEM_BYTES);

    proj_kernel<<<128, 256>>>(f1, f2, sw0);
    topk_kernel<<<1024, 256>>>(f1, f2, sb0, sg, sbe, smn, sv, sw1);
    dim3 grid(32, 16, 2);
    cls_kernel<<<grid, 256, SMEM_BYTES>>>(
        cw0, cb0, cg, cbe, cm, cv, cw1, cb1, out);
}

// round 4
// speedup vs baseline: 2.0697x; 1.2912x over previous
#include <cuda_runtime.h>
#include <cuda_fp16.h>
#include <cstdint>
#include <math.h>

#define D   128
#define N   256
#define BSZ 2
#define KNB 3
#define EPSF 1e-5f
#define NEG_INF (-3.402823466e38f)

// ---------------- scratch (no allocs allowed) ----------------
__device__ float g_P [2][BSZ][N][D];          // i-side sim projection
__device__ float g_Q [2][BSZ][N][D];          // j-side sim projection
__device__ float g_A [2][BSZ][N][D];          // absorbed features
__device__ float g_Nb[2][BSZ][N][KNB][D];     // gathered neighbor feats (ordered!)

// ---------------- helpers ----------------
__device__ __forceinline__ void mma16(float c[4], const uint32_t a[4],
                                      uint32_t b0, uint32_t b1){
    asm volatile(
        "mma.sync.aligned.m16n8k16.row.col.f32.f16.f16.f32 "
        "{%0,%1,%2,%3}, {%4,%5,%6,%7}, {%8,%9}, {%0,%1,%2,%3};\n"
        : "+f"(c[0]), "+f"(c[1]), "+f"(c[2]), "+f"(c[3])
        : "r"(a[0]), "r"(a[1]), "r"(a[2]), "r"(a[3]), "r"(b0), "r"(b1));
}

__device__ __forceinline__ void ldm4(uint32_t r[4], uint32_t addr){
    asm volatile("ldmatrix.sync.aligned.m8n8.x4.shared.b16 {%0,%1,%2,%3}, [%4];"
        : "=r"(r[0]), "=r"(r[1]), "=r"(r[2]), "=r"(r[3]) : "r"(addr));
}

__device__ __forceinline__ uint32_t ad2(uint32_t a, uint32_t b){
    __half2 ha = *reinterpret_cast<__half2*>(&a);
    __half2 hb = *reinterpret_cast<__half2*>(&b);
    __half2 r  = __habs2(__hsub2(ha, hb));
    return *reinterpret_cast<uint32_t*>(&r);
}

// ---------------- K1: P = f @ W0[:D], Q = f @ W0[D:]  (exact fp32) ----------------
// grid 64 = which(2) x 32 row-groups of 32 rows.  W-half staged in smem (64KB).
#define PR_FPAD 36
#define PR_SMEM_BYTES (D * D * 4 + D * PR_FPAD * 4)
__global__ void __launch_bounds__(256, 1) proj_kernel(
        const float* __restrict__ f1, const float* __restrict__ f2,
        const float* __restrict__ sw0){
    extern __shared__ float pms[];
    float* Wsm = pms;                 // [c*128 + d]
    float* fsT = pms + D * D;         // [c][PR_FPAD] transposed feats (32 rows)
    int t = threadIdx.x;
    int which = blockIdx.x >> 5;      // 0 -> P, 1 -> Q
    int row0 = (blockIdx.x & 31) * 32;                // global row in [0,1024)
    int f = row0 >> 9, b = (row0 >> 8) & 1, i0 = row0 & 255;
    const float* featb = (f == 0 ? f1 : f2) + b * N * D;

    for (int e = t * 4; e < D * D; e += 1024)
        *(float4*)&Wsm[e] = *(const float4*)&sw0[which * D * D + e];
    // fsT[c][r]: c-major so STS is conflict-free (LDG uncoalesced but tiny)
    for (int e = t; e < 32 * D; e += 256){
        int r = e & 31, c = e >> 5;
        fsT[c * PR_FPAD + r] = featb[(i0 + r) * D + c];
    }
    __syncthreads();

    int d = t & 127, rbase = (t >> 7) * 16;
    float acc[16];
    #pragma unroll
    for (int r = 0; r < 16; r++) acc[r] = 0.f;
    #pragma unroll 4
    for (int c = 0; c < D; c++){
        float w = Wsm[c * D + d];
        const float* fr = &fsT[c * PR_FPAD + rbase];
        float4 fa = *(const float4*)(fr);
        float4 fb = *(const float4*)(fr + 4);
        float4 fc = *(const float4*)(fr + 8);
        float4 fd = *(const float4*)(fr + 12);
        acc[0]  = fmaf(fa.x, w, acc[0]);  acc[1]  = fmaf(fa.y, w, acc[1]);
        acc[2]  = fmaf(fa.z, w, acc[2]);  acc[3]  = fmaf(fa.w, w, acc[3]);
        acc[4]  = fmaf(fb.x, w, acc[4]);  acc[5]  = fmaf(fb.y, w, acc[5]);
        acc[6]  = fmaf(fb.z, w, acc[6]);  acc[7]  = fmaf(fb.w, w, acc[7]);
        acc[8]  = fmaf(fc.x, w, acc[8]);  acc[9]  = fmaf(fc.y, w, acc[9]);
        acc[10] = fmaf(fc.z, w, acc[10]); acc[11] = fmaf(fc.w, w, acc[11]);
        acc[12] = fmaf(fd.x, w, acc[12]); acc[13] = fmaf(fd.y, w, acc[13]);
        acc[14] = fmaf(fd.z, w, acc[14]); acc[15] = fmaf(fd.w, w, acc[15]);
    }
    float* dst = which ? &g_Q[f][b][0][0] : &g_P[f][b][0][0];
    #pragma unroll
    for (int r = 0; r < 16; r++)
        dst[(i0 + rbase + r) * D + d] = acc[r];
}

// ---------------- K2: 4 i's per block: sim rows -> top3 -> gather/absorb ----------------
__global__ void topk_kernel(const float* __restrict__ f1, const float* __restrict__ f2,
        const float* __restrict__ sb0, const float* __restrict__ sg,
        const float* __restrict__ sbe, const float* __restrict__ smn,
        const float* __restrict__ sv,  const float* __restrict__ sw1){
    int gb = blockIdx.x;                       // 256 blocks
    int f = gb >> 7, b = (gb >> 6) & 1, i0 = (gb & 63) * 4;
    __shared__ float Ps[4][D], ss[D], tt[D], w1s[D];
    __shared__ float wv[8]; __shared__ int wi[8];
    __shared__ int bidx[4][KNB];
    int t = threadIdx.x, lane = t & 31, warp = t >> 5;
    if (t < D){
        float s = sg[t] * rsqrtf(sv[t] + EPSF);
        ss[t]  = s;
        tt[t]  = (sb0[t] - smn[t]) * s + sbe[t];
        w1s[t] = sw1[t];
        #pragma unroll
        for (int r = 0; r < 4; r++) Ps[r][t] = g_P[f][b][i0 + r][t];
    }
    __syncthreads();
    // thread t == candidate j, exact fp32 sims for 4 query rows
    const float* Qrow = &g_Q[f][b][t][0];
    float simv[4] = {0.f, 0.f, 0.f, 0.f};
    #pragma unroll 4
    for (int d = 0; d < D; d += 4){
        float4 q = *(const float4*)(Qrow + d);
        float s0 = ss[d], s1 = ss[d+1], s2 = ss[d+2], s3 = ss[d+3];
        float t0 = tt[d], t1 = tt[d+1], t2 = tt[d+2], t3 = tt[d+3];
        float w0 = w1s[d], w1 = w1s[d+1], w2 = w1s[d+2], w3 = w1s[d+3];
        #pragma unroll
        for (int r = 0; r < 4; r++){
            float h0 = (Ps[r][d]   + q.x) * s0 + t0;
            float h1 = (Ps[r][d+1] + q.y) * s1 + t1;
            float h2 = (Ps[r][d+2] + q.z) * s2 + t2;
            float h3 = (Ps[r][d+3] + q.w) * s3 + t3;
            simv[r] += fmaxf(h0, 0.f) * w0 + fmaxf(h1, 0.f) * w1
                     + fmaxf(h2, 0.f) * w2 + fmaxf(h3, 0.f) * w3;
        }
    }
    #pragma unroll
    for (int r = 0; r < 4; r++) if (t == i0 + r) simv[r] = NEG_INF;   // exclude self

    for (int r = 0; r < 4; r++){
        for (int k = 0; k < KNB; k++){
            float v = simv[r]; int idx = t;
            #pragma unroll
            for (int off = 16; off; off >>= 1){
                float ov = __shfl_down_sync(0xffffffffu, v, off);
                int   oi = __shfl_down_sync(0xffffffffu, idx, off);
                if (ov > v || (ov == v && oi < idx)){ v = ov; idx = oi; }
            }
            if (lane == 0){ wv[warp] = v; wi[warp] = idx; }
            __syncthreads();
            if (warp == 0){
                float v2 = (lane < 8) ? wv[lane] : NEG_INF;
                int   i2 = (lane < 8) ? wi[lane] : 0x7fffffff;
                #pragma unroll
                for (int off = 4; off; off >>= 1){
                    float ov = __shfl_down_sync(0xffffffffu, v2, off);
                    int   oi = __shfl_down_sync(0xffffffffu, i2, off);
                    if (ov > v2 || (ov == v2 && oi < i2)){ v2 = ov; i2 = oi; }
                }
                if (lane == 0) bidx[r][k] = i2;
            }
            __syncthreads();
            if (t == bidx[r][k]) simv[r] = NEG_INF;
        }
    }
    const float* featb = (f == 0 ? f1 : f2) + b * N * D;
    if (t < D){
        #pragma unroll
        for (int r = 0; r < 4; r++){
            int i = i0 + r;
            int k0 = bidx[r][0], k1 = bidx[r][1], k2 = bidx[r][2];
            float n0 = featb[k0 * D + t], n1 = featb[k1 * D + t], n2 = featb[k2 * D + t];
            g_Nb[f][b][i][0][t] = n0;
            g_Nb[f][b][i][1][t] = n1;
            g_Nb[f][b][i][2][t] = n2;
            g_A[f][b][i][t] = featb[i * D + t] + 0.5f * ((n0 + n1 + n2) * (1.f / 3.f));
        }
    }
}

// ---------------- K3: fused classifier, fp16 MMA + fp16 register-tiled X build ----------------
// smem bytes:
//   Wt  (half)  [128 d][136 kpad]     34816   A operand
//   Xs  (half)  [128 pair][136 kpad]  34816   B operand
//   Ush2(half2) [16 i][68 pad]         4352
//   Vsh2(half2) [ 8 j][68 pad]         2176
//   logit 512 | ps/pt/pw1 512 each
#define OFF_WT 0
#define OFF_XS 34816
#define OFF_US 69632
#define OFF_VS 73984
#define OFF_LG 76160
#define OFF_PS 76672
#define OFF_PT 77184
#define OFF_PW 77696
#define SMEM_BYTES 78208
#define KPAD 136
#define UPAD 68

__global__ void __launch_bounds__(256, 2) cls_kernel(
    const float* __restrict__ cw0, const float* __restrict__ cb0,
    const float* __restrict__ cg,  const float* __restrict__ cbe,
    const float* __restrict__ cm,  const float* __restrict__ cv,
    const float* __restrict__ cw1, const float* __restrict__ cb1,
    float* __restrict__ out)
{
    extern __shared__ char smb[];
    half*     Wt    = (half*)    (smb + OFF_WT);
    half*     Xs    = (half*)    (smb + OFF_XS);
    uint32_t* Ush2  = (uint32_t*)(smb + OFF_US);
    uint32_t* Vsh2  = (uint32_t*)(smb + OFF_VS);
    float*    logit = (float*)   (smb + OFF_LG);
    float*    ps    = (float*)   (smb + OFF_PS);
    float*    pt    = (float*)   (smb + OFF_PT);
    float*    pw1   = (float*)   (smb + OFF_PW);
    uint32_t wt_s = (uint32_t)__cvta_generic_to_shared(Wt);
    uint32_t xs_s = (uint32_t)__cvta_generic_to_shared(Xs);

    int t = threadIdx.x;
    int b = blockIdx.z, i0 = blockIdx.y * 16, j0 = blockIdx.x * 8;
    int lane = t & 31, warp = t >> 5;
    int gid = lane >> 2, tig = lane & 3;
    int warp_m = warp & 3, warp_n = warp >> 2;

    // stage Wt[d][k] = cw0[k*D+d] as fp16 (once per block)
    for (int e = t; e < D * D; e += 256){
        int k = e >> 7, d = e & 127;
        Wt[d * KPAD + k] = __float2half_rn(cw0[e]);
    }
    if (t < D){
        float s = cg[t] * rsqrtf(cv[t] + EPSF);
        ps[t]  = s;
        pt[t]  = (cb0[t] - cm[t]) * s + cbe[t];
        pw1[t] = cw1[t];
    }
    float b1v = cb1[0];
    float accPair = 0.f;

    // ldmatrix addressing (same layout as before)
    int a_row_base = warp_m * 32 + (lane & 15);
    int a_col_off  = (lane >> 4) << 3;
    int b_row_off = (lane & 7) + (((lane >> 4) & 1) << 3);
    int b_col_off = ((lane >> 3) & 1) << 3;

    // build-phase thread mapping: (2 i) x (4 j) x (8 k) chunks
    int g2 = t >> 4, kO = t & 15;
    int ib = (g2 >> 1) * 2;         // 0..14
    int jb = (g2 & 1) * 4;          // 0 or 4

    for (int ch = 0; ch < 4; ch++){
        const float* Ubase; const float* Vbase; int rstride;
        if (ch == 0){ Ubase = &g_A[0][b][0][0];          Vbase = &g_A[1][b][0][0];          rstride = D; }
        else        { Ubase = &g_Nb[0][b][0][ch-1][0];   Vbase = &g_Nb[1][b][0][ch-1][0];   rstride = KNB * D; }
        __syncthreads();
        // stage U,V tiles as half2
        for (int e = t; e < 16 * 64; e += 256){
            int r = e >> 6, c = e & 63;
            float2 fv = *(const float2*)(Ubase + (i0 + r) * rstride + 2 * c);
            __half2 h = __floats2half2_rn(fv.x, fv.y);
            Ush2[r * UPAD + c] = *(uint32_t*)&h;
        }
        for (int e = t; e < 8 * 64; e += 256){
            int r = e >> 6, c = e & 63;
            float2 fv = *(const float2*)(Vbase + (j0 + r) * rstride + 2 * c);
            __half2 h = __floats2half2_rn(fv.x, fv.y);
            Vsh2[r * UPAD + c] = *(uint32_t*)&h;
        }
        if (t < 128) logit[t] = b1v;
        __syncthreads();

        // register-tiled X build: 8 STS.128 per thread
        {
            uint4 u[2], v[4];
            u[0] = *(const uint4*)(Ush2 +  ib      * UPAD + kO * 4);
            u[1] = *(const uint4*)(Ush2 + (ib + 1) * UPAD + kO * 4);
            #pragma unroll
            for (int jj = 0; jj < 4; jj++)
                v[jj] = *(const uint4*)(Vsh2 + (jb + jj) * UPAD + kO * 4);
            #pragma unroll
            for (int ii = 0; ii < 2; ii++){
                #pragma unroll
                for (int jj = 0; jj < 4; jj++){
                    int pair = (ib + ii) * 8 + jb + jj;
                    uint4 x;
                    x.x = ad2(u[ii].x, v[jj].x);
                    x.y = ad2(u[ii].y, v[jj].y);
                    x.z = ad2(u[ii].z, v[jj].z);
                    x.w = ad2(u[ii].w, v[jj].w);
                    *(uint4*)(Xs + pair * KPAD + kO * 8) = x;
                }
            }
        }
        __syncthreads();

        float cacc[2][8][4];
        #pragma unroll
        for (int mt = 0; mt < 2; mt++)
            #pragma unroll
            for (int nt = 0; nt < 8; nt++)
                #pragma unroll
                for (int q = 0; q < 4; q++) cacc[mt][nt][q] = 0.f;

        #pragma unroll 1
        for (int ks = 0; ks < 8; ks++){
            int k0 = ks * 16;
            uint32_t aW[2][4];
            #pragma unroll
            for (int mt = 0; mt < 2; mt++){
                uint32_t addr = wt_s + ((a_row_base + mt * 16) * KPAD + k0 + a_col_off) * 2;
                ldm4(aW[mt], addr);
            }
            #pragma unroll
            for (int ntp = 0; ntp < 4; ntp++){
                int n0 = warp_n * 64 + ntp * 16;
                uint32_t bX[4];
                uint32_t addr = xs_s + ((n0 + b_row_off) * KPAD + k0 + b_col_off) * 2;
                ldm4(bX, addr);
                mma16(cacc[0][ntp * 2],     aW[0], bX[0], bX[1]);
                mma16(cacc[1][ntp * 2],     aW[1], bX[0], bX[1]);
                mma16(cacc[0][ntp * 2 + 1], aW[0], bX[2], bX[3]);
                mma16(cacc[1][ntp * 2 + 1], aW[1], bX[2], bX[3]);
            }
        }

        // epilogue: fold BN+ReLU+w1 over d, reduce
        float part0[8], part1[8];
        #pragma unroll
        for (int nt = 0; nt < 8; nt++){ part0[nt] = 0.f; part1[nt] = 0.f; }
        #pragma unroll
        for (int mt = 0; mt < 2; mt++){
            int d0 = warp_m * 32 + mt * 16 + gid, d1 = d0 + 8;
            float s0 = ps[d0], t0 = pt[d0], w0 = pw1[d0];
            float s1 = ps[d1], t1 = pt[d1], w1 = pw1[d1];
            #pragma unroll
            for (int nt = 0; nt < 8; nt++){
                float* c = cacc[mt][nt];
                part0[nt] += fmaxf(c[0] * s0 + t0, 0.f) * w0 + fmaxf(c[2] * s1 + t1, 0.f) * w1;
                part1[nt] += fmaxf(c[1] * s0 + t0, 0.f) * w0 + fmaxf(c[3] * s1 + t1, 0.f) * w1;
            }
        }
        #pragma unroll
        for (int nt = 0; nt < 8; nt++){
            #pragma unroll
            for (int off = 4; off <= 16; off <<= 1){
                part0[nt] += __shfl_xor_sync(0xffffffffu, part0[nt], off);
                part1[nt] += __shfl_xor_sync(0xffffffffu, part1[nt], off);
            }
        }
        if (gid == 0){
            #pragma unroll
            for (int nt = 0; nt < 8; nt++){
                int p = warp_n * 64 + nt * 8 + 2 * tig;
                atomicAdd(&logit[p],     part0[nt]);
                atomicAdd(&logit[p + 1], part1[nt]);
            }
        }
        __syncthreads();
        if (t < 128){
            float sc = 1.f / (1.f + expf(-logit[t]));
            accPair += (ch == 0 ? 0.5f : (1.f / 6.f)) * sc;
        }
    }
    if (t < 128){
        int il = t >> 3, jl = t & 7;
        out[(b * N + i0 + il) * N + (j0 + jl)] = accPair;
    }
}

// ---------------- launch ----------------
extern "C" void kernel_launch(void* const* d_in, const int* in_sizes, int n_in,
                              void* d_out, int out_size){
    const float* f1  = (const float*)d_in[0];
    const float* f2  = (const float*)d_in[1];
    const float* sw0 = (const float*)d_in[2];
    const float* sb0 = (const float*)d_in[3];
    const float* sg  = (const float*)d_in[4];
    const float* sbe = (const float*)d_in[5];
    const float* smn = (const float*)d_in[6];
    const float* sv  = (const float*)d_in[7];
    const float* sw1 = (const float*)d_in[8];
    /* d_in[9] = sim_b1: rank-invariant, unused */
    const float* cw0 = (const float*)d_in[10];
    const float* cb0 = (const float*)d_in[11];
    const float* cg  = (const float*)d_in[12];
    const float* cbe = (const float*)d_in[13];
    const float* cm  = (const float*)d_in[14];
    const float* cv  = (const float*)d_in[15];
    const float* cw1 = (const float*)d_in[16];
    const float* cb1 = (const float*)d_in[17];
    float* out = (float*)d_out;

    cudaFuncSetAttribute(proj_kernel, cudaFuncAttributeMaxDynamicSharedMemorySize,
                         PR_SMEM_BYTES);
    cudaFuncSetAttribute(cls_kernel, cudaFuncAttributeMaxDynamicSharedMemorySize,
                         SMEM_BYTES);

    proj_kernel<<<64, 256, PR_SMEM_BYTES>>>(f1, f2, sw0);
    topk_kernel<<<256, 256>>>(f1, f2, sb0, sg, sbe, smn, sv, sw1);
    dim3 grid(32, 16, 2);
    cls_kernel<<<grid, 256, SMEM_BYTES>>>(
        cw0, cb0, cg, cbe, cm, cv, cw1, cb1, out);
}

// round 6
// speedup vs baseline: 3.1236x; 1.5092x over previous
#include <cuda_runtime.h>
#include <cuda_fp16.h>
#include <cstdint>
#include <math.h>

#define D   128
#define N   256
#define BSZ 2
#define KNB 3
#define EPSF 1e-5f
#define NEG_INF (-3.402823466e38f)

// ---------------- scratch (no allocs allowed) ----------------
__device__ float g_P [2][BSZ][N][D];
__device__ float g_Q [2][BSZ][N][D];
__device__ float g_A [2][BSZ][N][D];
__device__ int   g_Idx[2][BSZ][N][KNB];
__device__ float g_S [2][BSZ][N][N];   // [0]=anchor sigmoid, [1]=raw-pair sigmoid

// ---------------- mma.sync / ldmatrix helpers (fp16, m16n8k16) ----------------
__device__ __forceinline__ void mma16(float c[4], const uint32_t a[4],
                                      uint32_t b0, uint32_t b1){
    asm volatile(
        "mma.sync.aligned.m16n8k16.row.col.f32.f16.f16.f32 "
        "{%0,%1,%2,%3}, {%4,%5,%6,%7}, {%8,%9}, {%0,%1,%2,%3};\n"
        : "+f"(c[0]), "+f"(c[1]), "+f"(c[2]), "+f"(c[3])
        : "r"(a[0]), "r"(a[1]), "r"(a[2]), "r"(a[3]), "r"(b0), "r"(b1));
}

__device__ __forceinline__ void ldm4(uint32_t r[4], uint32_t addr){
    asm volatile("ldmatrix.sync.aligned.m8n8.x4.shared.b16 {%0,%1,%2,%3}, [%4];"
        : "=r"(r[0]), "=r"(r[1]), "=r"(r[2]), "=r"(r[3]) : "r"(addr));
}

__device__ __forceinline__ uint32_t ad2(uint32_t a, uint32_t b){
    __half2 ha = *reinterpret_cast<__half2*>(&a);
    __half2 hb = *reinterpret_cast<__half2*>(&b);
    __half2 r  = __habs2(__hsub2(ha, hb));
    return *reinterpret_cast<uint32_t*>(&r);
}

// ---------------- K1: P = f @ W0[:D], Q = f @ W0[D:]  (exact fp32, high occupancy) ----------------
__global__ void proj_kernel(const float* __restrict__ f1, const float* __restrict__ f2,
                            const float* __restrict__ sw0){
    __shared__ float fs[4][D];
    int which = blockIdx.x >> 8;              // 0 -> P, 1 -> Q
    int grp = blockIdx.x & 255;
    int f = grp >> 7, b = (grp >> 6) & 1, i0 = (grp & 63) * 4;
    const float* featb = (f == 0 ? f1 : f2) + b * N * D;
    int d = threadIdx.x;                      // 128 threads
    for (int e = d; e < 4 * D; e += 128){
        int r = e >> 7, c = e & 127;
        fs[r][c] = featb[(i0 + r) * D + c];
    }
    __syncthreads();
    const float* wb = sw0 + which * D * D + d;
    float a0 = 0.f, a1 = 0.f, a2 = 0.f, a3 = 0.f;
    #pragma unroll 8
    for (int c = 0; c < D; c++){
        float w = wb[c * D];
        a0 = fmaf(fs[0][c], w, a0);
        a1 = fmaf(fs[1][c], w, a1);
        a2 = fmaf(fs[2][c], w, a2);
        a3 = fmaf(fs[3][c], w, a3);
    }
    float* dst = which ? &g_Q[f][b][0][0] : &g_P[f][b][0][0];
    dst[(i0    ) * D + d] = a0;
    dst[(i0 + 1) * D + d] = a1;
    dst[(i0 + 2) * D + d] = a2;
    dst[(i0 + 3) * D + d] = a3;
}

// ---------------- K2: 4 i's per block: sim rows -> top3 -> absorb + store indices ----------------
__global__ void topk_kernel(const float* __restrict__ f1, const float* __restrict__ f2,
        const float* __restrict__ sb0, const float* __restrict__ sg,
        const float* __restrict__ sbe, const float* __restrict__ smn,
        const float* __restrict__ sv,  const float* __restrict__ sw1){
    int gb = blockIdx.x;                       // 256 blocks
    int f = gb >> 7, b = (gb >> 6) & 1, i0 = (gb & 63) * 4;
    __shared__ float Ps[4][D], ss[D], tt[D], w1s[D];
    __shared__ float wv[8]; __shared__ int wi[8];
    __shared__ int bidx[4][KNB];
    int t = threadIdx.x, lane = t & 31, warp = t >> 5;
    if (t < D){
        float s = sg[t] * rsqrtf(sv[t] + EPSF);
        ss[t]  = s;
        tt[t]  = (sb0[t] - smn[t]) * s + sbe[t];
        w1s[t] = sw1[t];
        #pragma unroll
        for (int r = 0; r < 4; r++) Ps[r][t] = g_P[f][b][i0 + r][t];
    }
    __syncthreads();
    const float* Qrow = &g_Q[f][b][t][0];
    float simv[4] = {0.f, 0.f, 0.f, 0.f};
    #pragma unroll 4
    for (int d = 0; d < D; d += 4){
        float4 q = *(const float4*)(Qrow + d);
        float s0 = ss[d], s1 = ss[d+1], s2 = ss[d+2], s3 = ss[d+3];
        float t0 = tt[d], t1 = tt[d+1], t2 = tt[d+2], t3 = tt[d+3];
        float w0 = w1s[d], w1 = w1s[d+1], w2 = w1s[d+2], w3 = w1s[d+3];
        #pragma unroll
        for (int r = 0; r < 4; r++){
            float h0 = (Ps[r][d]   + q.x) * s0 + t0;
            float h1 = (Ps[r][d+1] + q.y) * s1 + t1;
            float h2 = (Ps[r][d+2] + q.z) * s2 + t2;
            float h3 = (Ps[r][d+3] + q.w) * s3 + t3;
            simv[r] += fmaxf(h0, 0.f) * w0 + fmaxf(h1, 0.f) * w1
                     + fmaxf(h2, 0.f) * w2 + fmaxf(h3, 0.f) * w3;
        }
    }
    #pragma unroll
    for (int r = 0; r < 4; r++) if (t == i0 + r) simv[r] = NEG_INF;   // exclude self

    for (int r = 0; r < 4; r++){
        for (int k = 0; k < KNB; k++){
            float v = simv[r]; int idx = t;
            #pragma unroll
            for (int off = 16; off; off >>= 1){
                float ov = __shfl_down_sync(0xffffffffu, v, off);
                int   oi = __shfl_down_sync(0xffffffffu, idx, off);
                if (ov > v || (ov == v && oi < idx)){ v = ov; idx = oi; }
            }
            if (lane == 0){ wv[warp] = v; wi[warp] = idx; }
            __syncthreads();
            if (warp == 0){
                float v2 = (lane < 8) ? wv[lane] : NEG_INF;
                int   i2 = (lane < 8) ? wi[lane] : 0x7fffffff;
                #pragma unroll
                for (int off = 4; off; off >>= 1){
                    float ov = __shfl_down_sync(0xffffffffu, v2, off);
                    int   oi = __shfl_down_sync(0xffffffffu, i2, off);
                    if (ov > v2 || (ov == v2 && oi < i2)){ v2 = ov; i2 = oi; }
                }
                if (lane == 0) bidx[r][k] = i2;
            }
            __syncthreads();
            if (t == bidx[r][k]) simv[r] = NEG_INF;
        }
    }
    const float* featb = (f == 0 ? f1 : f2) + b * N * D;
    if (t < D){
        #pragma unroll
        for (int r = 0; r < 4; r++){
            int i = i0 + r;
            int k0 = bidx[r][0], k1 = bidx[r][1], k2 = bidx[r][2];
            float n0 = featb[k0 * D + t], n1 = featb[k1 * D + t], n2 = featb[k2 * D + t];
            g_A[f][b][i][t] = featb[i * D + t] + 0.5f * ((n0 + n1 + n2) * (1.f / 3.f));
        }
    }
    if (t < 4){
        #pragma unroll
        for (int k = 0; k < KNB; k++)
            g_Idx[f][b][i0 + t][k] = bidx[t][k];
    }
}

// ---------------- K3: pair-sigmoid GEMM (2 channels: absorbed-anchor + raw-S) ----------------
// smem layout (bytes):
#define OFF_PS   0
#define OFF_PT   512
#define OFF_PW   1024
#define OFF_US   1536     // Ush2: 16 x 68 uint32 = 4352
#define OFF_VS   5888     // Vsh2:  8 x 68 uint32 = 2176
#define OFF_WT   8192     // Wt fp16 [128 d][136] = 34816
#define OFF_XS   43008    // Xs fp16 [128 pair][136] = 34816
#define SMEM_BYTES 77824
#define KPAD 136
#define UPAD 68

__global__ void __launch_bounds__(256, 2) cls_kernel(
    const float* __restrict__ f1,  const float* __restrict__ f2,
    const float* __restrict__ cw0, const float* __restrict__ cb0,
    const float* __restrict__ cg,  const float* __restrict__ cbe,
    const float* __restrict__ cm,  const float* __restrict__ cv,
    const float* __restrict__ cw1, const float* __restrict__ cb1)
{
    extern __shared__ char smb[];
    float*    ps   = (float*)   (smb + OFF_PS);
    float*    pt   = (float*)   (smb + OFF_PT);
    float*    pw1  = (float*)   (smb + OFF_PW);
    uint32_t* Ush2 = (uint32_t*)(smb + OFF_US);
    uint32_t* Vsh2 = (uint32_t*)(smb + OFF_VS);
    half*     Wt   = (half*)    (smb + OFF_WT);
    half*     Xs   = (half*)    (smb + OFF_XS);
    uint32_t smem_base = (uint32_t)__cvta_generic_to_shared(smb);
    uint32_t wt_s = smem_base + OFF_WT;
    uint32_t xs_s = smem_base + OFF_XS;

    int t = threadIdx.x;
    int b = blockIdx.z, i0 = blockIdx.y * 16, j0 = blockIdx.x * 8;
    int lane = t & 31, warp = t >> 5;
    int gid = lane >> 2, tig = lane & 3;

    // stage Wt[d][k] = cw0[k*D+d] as fp16 (B operand, rows = d)
    for (int e = t; e < D * D; e += 256){
        int k = e >> 7, d = e & 127;
        Wt[d * KPAD + k] = __float2half_rn(cw0[e]);
    }
    if (t < D){
        float s = cg[t] * rsqrtf(cv[t] + EPSF);
        ps[t]  = s;
        pt[t]  = (cb0[t] - cm[t]) * s + cbe[t];
        pw1[t] = cw1[t];
    }
    float b1v = cb1[0];

    // ldmatrix addressing
    int a_row = warp * 16 + (lane & 15);            // A rows = pairs (16 per warp)
    int a_col_off = (lane >> 4) << 3;
    int b_row_off = (lane & 7) + (((lane >> 4) & 1) << 3);
    int b_col_off = ((lane >> 3) & 1) << 3;

    // build-phase thread mapping: (2 i) x (4 j) x (8 k) chunks
    int g2 = t >> 4, kO = t & 15;
    int ib = (g2 >> 1) * 2;
    int jb = (g2 & 1) * 4;

    #pragma unroll 1
    for (int ch = 0; ch < 2; ch++){
        const float* Ubase = (ch == 0) ? &g_A[0][b][0][0] : (f1 + b * N * D);
        const float* Vbase = (ch == 0) ? &g_A[1][b][0][0] : (f2 + b * N * D);

        __syncthreads();   // prev MMA (Xs reads) + prev build (Ush reads) complete
        // stage U (16 rows), V (8 rows) as half2
        for (int e = t; e < 16 * 64; e += 256){
            int r = e >> 6, c = e & 63;
            float2 fv = *(const float2*)(Ubase + (i0 + r) * D + 2 * c);
            __half2 h = __floats2half2_rn(fv.x, fv.y);
            Ush2[r * UPAD + c] = *(uint32_t*)&h;
        }
        for (int e = t; e < 8 * 64; e += 256){
            int r = e >> 6, c = e & 63;
            float2 fv = *(const float2*)(Vbase + (j0 + r) * D + 2 * c);
            __half2 h = __floats2half2_rn(fv.x, fv.y);
            Vsh2[r * UPAD + c] = *(uint32_t*)&h;
        }
        __syncthreads();

        // register-tiled X build: pair = il*8+jl, 8 STS.128 per thread
        {
            uint4 u0 = *(const uint4*)(Ush2 +  ib      * UPAD + kO * 4);
            uint4 u1 = *(const uint4*)(Ush2 + (ib + 1) * UPAD + kO * 4);
            #pragma unroll
            for (int jj = 0; jj < 4; jj++){
                uint4 v = *(const uint4*)(Vsh2 + (jb + jj) * UPAD + kO * 4);
                uint4 x0, x1;
                x0.x = ad2(u0.x, v.x); x0.y = ad2(u0.y, v.y); x0.z = ad2(u0.z, v.z); x0.w = ad2(u0.w, v.w);
                x1.x = ad2(u1.x, v.x); x1.y = ad2(u1.y, v.y); x1.z = ad2(u1.z, v.z); x1.w = ad2(u1.w, v.w);
                *(uint4*)(Xs + ( ib      * 8 + jb + jj) * KPAD + kO * 8) = x0;
                *(uint4*)(Xs + ((ib + 1) * 8 + jb + jj) * KPAD + kO * 8) = x1;
            }
        }
        __syncthreads();

        float cacc[16][4];
        #pragma unroll
        for (int nt = 0; nt < 16; nt++)
            #pragma unroll
            for (int q = 0; q < 4; q++) cacc[nt][q] = 0.f;

        #pragma unroll 1
        for (int ks = 0; ks < 8; ks++){
            int k0 = ks * 16;
            uint32_t aX[4];
            ldm4(aX, xs_s + (a_row * KPAD + k0 + a_col_off) * 2);
            #pragma unroll
            for (int ng = 0; ng < 8; ng++){
                uint32_t bW[4];
                ldm4(bW, wt_s + ((ng * 16 + b_row_off) * KPAD + k0 + b_col_off) * 2);
                mma16(cacc[ng * 2],     aX, bW[0], bW[1]);
                mma16(cacc[ng * 2 + 1], aX, bW[2], bW[3]);
            }
        }

        // epilogue: rows = pairs (gid, gid+8), cols = d; reduce over d in-thread + 2 shfl
        float l0 = 0.f, l1 = 0.f;
        #pragma unroll
        for (int nt = 0; nt < 16; nt++){
            int d0 = (nt >> 1) * 16 + (nt & 1) * 8 + 2 * tig;
            float s0 = ps[d0], t0 = pt[d0], w0 = pw1[d0];
            float s1 = ps[d0 + 1], t1 = pt[d0 + 1], w1 = pw1[d0 + 1];
            float* c = cacc[nt];
            l0 += fmaxf(c[0] * s0 + t0, 0.f) * w0 + fmaxf(c[1] * s1 + t1, 0.f) * w1;
            l1 += fmaxf(c[2] * s0 + t0, 0.f) * w0 + fmaxf(c[3] * s1 + t1, 0.f) * w1;
        }
        l0 += __shfl_xor_sync(0xffffffffu, l0, 1);
        l0 += __shfl_xor_sync(0xffffffffu, l0, 2);
        l1 += __shfl_xor_sync(0xffffffffu, l1, 1);
        l1 += __shfl_xor_sync(0xffffffffu, l1, 2);
        if (tig == 0){
            float sc0 = 1.f / (1.f + expf(-(l0 + b1v)));
            float sc1 = 1.f / (1.f + expf(-(l1 + b1v)));
            // pair p0 = warp*16+gid -> il = 2*warp, jl = gid ; p1 -> il = 2*warp+1
            g_S[ch][b][i0 + 2 * warp    ][j0 + gid] = sc0;
            g_S[ch][b][i0 + 2 * warp + 1][j0 + gid] = sc1;
        }
    }
}

// ---------------- K4: combine anchor + gathered neighbor scores ----------------
__global__ void combine_kernel(float* __restrict__ out){
    int blk = blockIdx.x;             // 512 = b*256 + i
    int b = blk >> 8, i = blk & 255;
    int j = threadIdx.x;
    __shared__ int ia[KNB];
    if (j < KNB) ia[j] = g_Idx[0][b][i][j];
    __syncthreads();
    float sa = g_S[0][b][i][j];
    const int* bj = &g_Idx[1][b][j][0];
    int b0 = bj[0], b1 = bj[1], b2 = bj[2];
    float s = g_S[1][b][ia[0]][b0] + g_S[1][b][ia[1]][b1] + g_S[1][b][ia[2]][b2];
    out[(b * N + i) * N + j] = 0.5f * sa + (1.f / 6.f) * s;
}

// ---------------- launch ----------------
extern "C" void kernel_launch(void* const* d_in, const int* in_sizes, int n_in,
                              void* d_out, int out_size){
    const float* f1  = (const float*)d_in[0];
    const float* f2  = (const float*)d_in[1];
    const float* sw0 = (const float*)d_in[2];
    const float* sb0 = (const float*)d_in[3];
    const float* sg  = (const float*)d_in[4];
    const float* sbe = (const float*)d_in[5];
    const float* smn = (const float*)d_in[6];
    const float* sv  = (const float*)d_in[7];
    const float* sw1 = (const float*)d_in[8];
    /* d_in[9] = sim_b1: rank-invariant, unused */
    const float* cw0 = (const float*)d_in[10];
    const float* cb0 = (const float*)d_in[11];
    const float* cg  = (const float*)d_in[12];
    const float* cbe = (const float*)d_in[13];
    const float* cm  = (const float*)d_in[14];
    const float* cv  = (const float*)d_in[15];
    const float* cw1 = (const float*)d_in[16];
    const float* cb1 = (const float*)d_in[17];
    float* out = (float*)d_out;

    cudaFuncSetAttribute(cls_kernel, cudaFuncAttributeMaxDynamicSharedMemorySize,
                         SMEM_BYTES);

    proj_kernel<<<512, 128>>>(f1, f2, sw0);
    topk_kernel<<<256, 256>>>(f1, f2, sb0, sg, sbe, smn, sv, sw1);
    dim3 grid(32, 16, 2);
    cls_kernel<<<grid, 256, SMEM_BYTES>>>(
        f1, f2, cw0, cb0, cg, cbe, cm, cv, cw1, cb1);
    combine_kernel<<<512, 256>>>(out);
}

// round 7
// speedup vs baseline: 3.6254x; 1.1607x over previous
#include <cuda_runtime.h>
#include <cuda_fp16.h>
#include <cstdint>
#include <math.h>

#define D   128
#define N   256
#define BSZ 2
#define KNB 3
#define EPSF 1e-5f
#define NEG_INF (-3.402823466e38f)

// ---------------- scratch (no allocs allowed) ----------------
__device__ float g_P [2][BSZ][N][D];
__device__ float g_Q [2][BSZ][N][D];
__device__ float g_A [2][BSZ][N][D];
__device__ int   g_Idx[2][BSZ][N][KNB];
__device__ float g_S [2][BSZ][N][N];   // [0]=anchor sigmoid, [1]=raw-pair sigmoid
__device__ __half g_Wh[D * D];         // W0^T as fp16: g_Wh[d*128 + k] = cw0[k*128 + d]

// ---------------- mma.sync / ldmatrix helpers (fp16, m16n8k16) ----------------
__device__ __forceinline__ void mma16(float c[4], const uint32_t a[4],
                                      uint32_t b0, uint32_t b1){
    asm volatile(
        "mma.sync.aligned.m16n8k16.row.col.f32.f16.f16.f32 "
        "{%0,%1,%2,%3}, {%4,%5,%6,%7}, {%8,%9}, {%0,%1,%2,%3};\n"
        : "+f"(c[0]), "+f"(c[1]), "+f"(c[2]), "+f"(c[3])
        : "r"(a[0]), "r"(a[1]), "r"(a[2]), "r"(a[3]), "r"(b0), "r"(b1));
}

__device__ __forceinline__ void ldm4(uint32_t r[4], uint32_t addr){
    asm volatile("ldmatrix.sync.aligned.m8n8.x4.shared.b16 {%0,%1,%2,%3}, [%4];"
        : "=r"(r[0]), "=r"(r[1]), "=r"(r[2]), "=r"(r[3]) : "r"(addr));
}

__device__ __forceinline__ uint32_t ad2(uint32_t a, uint32_t b){
    __half2 ha = *reinterpret_cast<__half2*>(&a);
    __half2 hb = *reinterpret_cast<__half2*>(&b);
    __half2 r  = __habs2(__hsub2(ha, hb));
    return *reinterpret_cast<uint32_t*>(&r);
}

// ---------------- K0: one-time W0^T -> fp16 ----------------
__global__ void prep_w(const float* __restrict__ cw0){
    int e = blockIdx.x * 256 + threadIdx.x;   // 64 blocks x 256 = 16384
    int d = e >> 7, k = e & 127;
    g_Wh[d * D + k] = __float2half_rn(cw0[k * D + d]);
}

// ---------------- K1: P = f @ W0[:D], Q = f @ W0[D:]  (exact fp32) ----------------
__global__ void proj_kernel(const float* __restrict__ f1, const float* __restrict__ f2,
                            const float* __restrict__ sw0){
    __shared__ float fs[4][D];
    int which = blockIdx.x >> 8;
    int grp = blockIdx.x & 255;
    int f = grp >> 7, b = (grp >> 6) & 1, i0 = (grp & 63) * 4;
    const float* featb = (f == 0 ? f1 : f2) + b * N * D;
    int d = threadIdx.x;                      // 128 threads
    for (int e = d; e < 4 * D; e += 128){
        int r = e >> 7, c = e & 127;
        fs[r][c] = featb[(i0 + r) * D + c];
    }
    __syncthreads();
    const float* wb = sw0 + which * D * D + d;
    float a0 = 0.f, a1 = 0.f, a2 = 0.f, a3 = 0.f;
    #pragma unroll 8
    for (int c = 0; c < D; c++){
        float w = wb[c * D];
        a0 = fmaf(fs[0][c], w, a0);
        a1 = fmaf(fs[1][c], w, a1);
        a2 = fmaf(fs[2][c], w, a2);
        a3 = fmaf(fs[3][c], w, a3);
    }
    float* dst = which ? &g_Q[f][b][0][0] : &g_P[f][b][0][0];
    dst[(i0    ) * D + d] = a0;
    dst[(i0 + 1) * D + d] = a1;
    dst[(i0 + 2) * D + d] = a2;
    dst[(i0 + 3) * D + d] = a3;
}

// ---------------- K2: 4 i's per block: sim rows -> top3 -> absorb + indices ----------------
__global__ void topk_kernel(const float* __restrict__ f1, const float* __restrict__ f2,
        const float* __restrict__ sb0, const float* __restrict__ sg,
        const float* __restrict__ sbe, const float* __restrict__ smn,
        const float* __restrict__ sv,  const float* __restrict__ sw1){
    int gb = blockIdx.x;                       // 256 blocks
    int f = gb >> 7, b = (gb >> 6) & 1, i0 = (gb & 63) * 4;
    __shared__ float Ps[4][D], ss[D], tt[D], w1s[D];
    __shared__ float wv[8]; __shared__ int wi[8];
    __shared__ int bidx[4][KNB];
    int t = threadIdx.x, lane = t & 31, warp = t >> 5;
    if (t < D){
        float s = sg[t] * rsqrtf(sv[t] + EPSF);
        ss[t]  = s;
        tt[t]  = (sb0[t] - smn[t]) * s + sbe[t];
        w1s[t] = sw1[t];
        #pragma unroll
        for (int r = 0; r < 4; r++) Ps[r][t] = g_P[f][b][i0 + r][t];
    }
    __syncthreads();
    const float* Qrow = &g_Q[f][b][t][0];
    float simv[4] = {0.f, 0.f, 0.f, 0.f};
    #pragma unroll 4
    for (int d = 0; d < D; d += 4){
        float4 q = *(const float4*)(Qrow + d);
        float s0 = ss[d], s1 = ss[d+1], s2 = ss[d+2], s3 = ss[d+3];
        float t0 = tt[d], t1 = tt[d+1], t2 = tt[d+2], t3 = tt[d+3];
        float w0 = w1s[d], w1 = w1s[d+1], w2 = w1s[d+2], w3 = w1s[d+3];
        #pragma unroll
        for (int r = 0; r < 4; r++){
            float h0 = (Ps[r][d]   + q.x) * s0 + t0;
            float h1 = (Ps[r][d+1] + q.y) * s1 + t1;
            float h2 = (Ps[r][d+2] + q.z) * s2 + t2;
            float h3 = (Ps[r][d+3] + q.w) * s3 + t3;
            simv[r] += fmaxf(h0, 0.f) * w0 + fmaxf(h1, 0.f) * w1
                     + fmaxf(h2, 0.f) * w2 + fmaxf(h3, 0.f) * w3;
        }
    }
    #pragma unroll
    for (int r = 0; r < 4; r++) if (t == i0 + r) simv[r] = NEG_INF;

    for (int r = 0; r < 4; r++){
        for (int k = 0; k < KNB; k++){
            float v = simv[r]; int idx = t;
            #pragma unroll
            for (int off = 16; off; off >>= 1){
                float ov = __shfl_down_sync(0xffffffffu, v, off);
                int   oi = __shfl_down_sync(0xffffffffu, idx, off);
                if (ov > v || (ov == v && oi < idx)){ v = ov; idx = oi; }
            }
            if (lane == 0){ wv[warp] = v; wi[warp] = idx; }
            __syncthreads();
            if (warp == 0){
                float v2 = (lane < 8) ? wv[lane] : NEG_INF;
                int   i2 = (lane < 8) ? wi[lane] : 0x7fffffff;
                #pragma unroll
                for (int off = 4; off; off >>= 1){
                    float ov = __shfl_down_sync(0xffffffffu, v2, off);
                    int   oi = __shfl_down_sync(0xffffffffu, i2, off);
                    if (ov > v2 || (ov == v2 && oi < i2)){ v2 = ov; i2 = oi; }
                }
                if (lane == 0) bidx[r][k] = i2;
            }
            __syncthreads();
            if (t == bidx[r][k]) simv[r] = NEG_INF;
        }
    }
    const float* featb = (f == 0 ? f1 : f2) + b * N * D;
    if (t < D){
        #pragma unroll
        for (int r = 0; r < 4; r++){
            int i = i0 + r;
            int k0 = bidx[r][0], k1 = bidx[r][1], k2 = bidx[r][2];
            float n0 = featb[k0 * D + t], n1 = featb[k1 * D + t], n2 = featb[k2 * D + t];
            g_A[f][b][i][t] = featb[i * D + t] + 0.5f * ((n0 + n1 + n2) * (1.f / 3.f));
        }
    }
    if (t < 4){
        #pragma unroll
        for (int k = 0; k < KNB; k++)
            g_Idx[f][b][i0 + t][k] = bidx[t][k];
    }
}

// ---------------- K3: pair-sigmoid GEMM, 64-pair tiles, d-split warps, 4 blocks/SM ----------------
// XOR-swizzled smem: logical (row, chunk[16B]) -> phys row*256 + (chunk ^ (row&7))*16
#define OFF_PS   0
#define OFF_PT   512
#define OFF_PW   1024
#define OFF_LG   1536     // 64 floats
#define OFF_US   1792     // Ush2: 8 x 68 uint32 = 2176
#define OFF_VS   3968     // Vsh2: 8 x 68 uint32 = 2176
#define OFF_WT   6144     // Wt swizzled fp16 [128 d][128 k] = 32768
#define OFF_XS   38912    // Xs swizzled fp16 [64 pair][128 k] = 16384
#define SMEM_BYTES 55296
#define UPAD 68

__global__ void __launch_bounds__(256, 4) cls_kernel(
    const float* __restrict__ f1,  const float* __restrict__ f2,
    const float* __restrict__ cb0,
    const float* __restrict__ cg,  const float* __restrict__ cbe,
    const float* __restrict__ cm,  const float* __restrict__ cv,
    const float* __restrict__ cw1, const float* __restrict__ cb1)
{
    extern __shared__ char smb[];
    float*    ps    = (float*)   (smb + OFF_PS);
    float*    pt    = (float*)   (smb + OFF_PT);
    float*    pw1   = (float*)   (smb + OFF_PW);
    float*    logit = (float*)   (smb + OFF_LG);
    uint32_t* Ush2  = (uint32_t*)(smb + OFF_US);
    uint32_t* Vsh2  = (uint32_t*)(smb + OFF_VS);
    char*     Xs    = smb + OFF_XS;
    uint32_t smem_base = (uint32_t)__cvta_generic_to_shared(smb);
    uint32_t wt_s = smem_base + OFF_WT;
    uint32_t xs_s = smem_base + OFF_XS;

    int t = threadIdx.x;
    int b = blockIdx.z, i0 = blockIdx.y * 8, j0 = blockIdx.x * 8;
    int lane = t & 31, warp = t >> 5;
    int gid = lane >> 2, tig = lane & 3;
    int pg = warp >> 1, dg = warp & 1;       // 4 pair-groups x 2 d-groups

    // stage swizzled Wt from prepped fp16 (8 x LDG.128/STS.128 per thread)
    #pragma unroll
    for (int i = 0; i < 8; i++){
        int e = t + i * 256;                 // 2048 16B chunks
        int d = e >> 4, ck = e & 15;
        uint4 v = *(const uint4*)(g_Wh + d * D + ck * 8);
        *(uint4*)(smb + OFF_WT + d * 256 + ((ck ^ (d & 7)) << 4)) = v;
    }
    if (t < D){
        float s = cg[t] * rsqrtf(cv[t] + EPSF);
        ps[t]  = s;
        pt[t]  = (cb0[t] - cm[t]) * s + cbe[t];
        pw1[t] = cw1[t];
    }
    float b1v = cb1[0];

    // A (Xs) ldmatrix lane addressing: row fixed per warp
    int a_row = pg * 16 + (lane & 15);
    uint32_t a_base = xs_s + a_row * 256;
    int a_r7 = a_row & 7, a_hi = lane >> 4;
    // B (Wt): row fixed per ng
    int b_row_off = (lane & 7) + (((lane >> 4) & 1) << 3);
    int b_khi = (lane >> 3) & 1;
    uint32_t bw_base[4]; int bw_r7[4];
    #pragma unroll
    for (int ng = 0; ng < 4; ng++){
        int row = dg * 64 + ng * 16 + b_row_off;
        bw_base[ng] = wt_s + row * 256;
        bw_r7[ng]   = row & 7;
    }

    // build mapping: (1 i x 4 j x 16-chunk k) per thread
    int g2 = t >> 4, kO = t & 15;
    int ii = g2 >> 1, jb = (g2 & 1) * 4;

    #pragma unroll 1
    for (int ch = 0; ch < 2; ch++){
        const float* Ubase = (ch == 0) ? &g_A[0][b][0][0] : (f1 + b * N * D);
        const float* Vbase = (ch == 0) ? &g_A[1][b][0][0] : (f2 + b * N * D);

        __syncthreads();   // prev channel's Xs reads + logit reads complete
        for (int e = t; e < 8 * 64; e += 256){
            int r = e >> 6, c = e & 63;
            float2 fu = *(const float2*)(Ubase + (i0 + r) * D + 2 * c);
            float2 fv = *(const float2*)(Vbase + (j0 + r) * D + 2 * c);
            __half2 hu = __floats2half2_rn(fu.x, fu.y);
            __half2 hv = __floats2half2_rn(fv.x, fv.y);
            Ush2[r * UPAD + c] = *(uint32_t*)&hu;
            Vsh2[r * UPAD + c] = *(uint32_t*)&hv;
        }
        if (t < 64) logit[t] = b1v;
        __syncthreads();

        // build X = |U_i - V_j| into swizzled tile: 4 STS.128 per thread
        {
            uint4 u = *(const uint4*)(Ush2 + ii * UPAD + kO * 4);
            #pragma unroll
            for (int jj = 0; jj < 4; jj++){
                uint4 v = *(const uint4*)(Vsh2 + (jb + jj) * UPAD + kO * 4);
                uint4 x;
                x.x = ad2(u.x, v.x); x.y = ad2(u.y, v.y);
                x.z = ad2(u.z, v.z); x.w = ad2(u.w, v.w);
                int pair = ii * 8 + jb + jj;
                *(uint4*)(Xs + pair * 256 + ((kO ^ (pair & 7)) << 4)) = x;
            }
        }
        __syncthreads();

        float cacc[8][4];
        #pragma unroll
        for (int nt = 0; nt < 8; nt++)
            #pragma unroll
            for (int q = 0; q < 4; q++) cacc[nt][q] = 0.f;

        #pragma unroll 1
        for (int ks = 0; ks < 8; ks++){
            int ck = 2 * ks;
            uint32_t aX[4];
            ldm4(aX, a_base + (((ck + a_hi) ^ a_r7) << 4));
            #pragma unroll
            for (int ng = 0; ng < 4; ng++){
                uint32_t bW[4];
                ldm4(bW, bw_base[ng] + (((ck + b_khi) ^ bw_r7[ng]) << 4));
                mma16(cacc[ng * 2],     aX, bW[0], bW[1]);
                mma16(cacc[ng * 2 + 1], aX, bW[2], bW[3]);
            }
        }

        // epilogue: rows = pairs (gid, gid+8), cols = d (this warp's 64-d half)
        float l0 = 0.f, l1 = 0.f;
        #pragma unroll
        for (int nt = 0; nt < 8; nt++){
            int d0 = dg * 64 + (nt >> 1) * 16 + (nt & 1) * 8 + 2 * tig;
            float s0 = ps[d0], t0 = pt[d0], w0 = pw1[d0];
            float s1 = ps[d0 + 1], t1 = pt[d0 + 1], w1 = pw1[d0 + 1];
            float* c = cacc[nt];
            l0 += fmaxf(c[0] * s0 + t0, 0.f) * w0 + fmaxf(c[1] * s1 + t1, 0.f) * w1;
            l1 += fmaxf(c[2] * s0 + t0, 0.f) * w0 + fmaxf(c[3] * s1 + t1, 0.f) * w1;
        }
        l0 += __shfl_xor_sync(0xffffffffu, l0, 1);
        l0 += __shfl_xor_sync(0xffffffffu, l0, 2);
        l1 += __shfl_xor_sync(0xffffffffu, l1, 1);
        l1 += __shfl_xor_sync(0xffffffffu, l1, 2);
        if (tig == 0){
            atomicAdd(&logit[pg * 16 + gid],     l0);
            atomicAdd(&logit[pg * 16 + gid + 8], l1);
        }
        __syncthreads();
        if (t < 64){
            float sc = 1.f / (1.f + expf(-logit[t]));
            g_S[ch][b][i0 + (t >> 3)][j0 + (t & 7)] = sc;
        }
    }
}

// ---------------- K4: combine anchor + gathered neighbor scores ----------------
__global__ void combine_kernel(float* __restrict__ out){
    int blk = blockIdx.x;             // 512 = b*256 + i
    int b = blk >> 8, i = blk & 255;
    int j = threadIdx.x;
    __shared__ int ia[KNB];
    if (j < KNB) ia[j] = g_Idx[0][b][i][j];
    __syncthreads();
    float sa = g_S[0][b][i][j];
    const int* bj = &g_Idx[1][b][j][0];
    int b0 = bj[0], b1 = bj[1], b2 = bj[2];
    float s = g_S[1][b][ia[0]][b0] + g_S[1][b][ia[1]][b1] + g_S[1][b][ia[2]][b2];
    out[(b * N + i) * N + j] = 0.5f * sa + (1.f / 6.f) * s;
}

// ---------------- launch ----------------
extern "C" void kernel_launch(void* const* d_in, const int* in_sizes, int n_in,
                              void* d_out, int out_size){
    const float* f1  = (const float*)d_in[0];
    const float* f2  = (const float*)d_in[1];
    const float* sw0 = (const float*)d_in[2];
    const float* sb0 = (const float*)d_in[3];
    const float* sg  = (const float*)d_in[4];
    const float* sbe = (const float*)d_in[5];
    const float* smn = (const float*)d_in[6];
    const float* sv  = (const float*)d_in[7];
    const float* sw1 = (const float*)d_in[8];
    /* d_in[9] = sim_b1: rank-invariant, unused */
    const float* cw0 = (const float*)d_in[10];
    const float* cb0 = (const float*)d_in[11];
    const float* cg  = (const float*)d_in[12];
    const float* cbe = (const float*)d_in[13];
    const float* cm  = (const float*)d_in[14];
    const float* cv  = (const float*)d_in[15];
    const float* cw1 = (const float*)d_in[16];
    const float* cb1 = (const float*)d_in[17];
    float* out = (float*)d_out;

    cudaFuncSetAttribute(cls_kernel, cudaFuncAttributeMaxDynamicSharedMemorySize,
                         SMEM_BYTES);

    prep_w<<<64, 256>>>(cw0);
    proj_kernel<<<512, 128>>>(f1, f2, sw0);
    topk_kernel<<<256, 256>>>(f1, f2, sb0, sg, sbe, smn, sv, sw1);
    dim3 grid(32, 32, 2);
    cls_kernel<<<grid, 256, SMEM_BYTES>>>(
        f1, f2, cb0, cg, cbe, cm, cv, cw1, cb1);
    combine_kernel<<<512, 256>>>(out);
}

// round 8
// speedup vs baseline: 3.7142x; 1.0245x over previous
#include <cuda_runtime.h>
#include <cuda_fp16.h>
#include <cstdint>
#include <math.h>

#define D   128
#define N   256
#define BSZ 2
#define KNB 3
#define EPSF 1e-5f
#define NEG_INF (-3.402823466e38f)

// ---------------- scratch (no allocs allowed) ----------------
__device__ float g_P [2][BSZ][N][D];
__device__ float g_Q [2][BSZ][N][D];
__device__ float g_A [2][BSZ][N][D];
__device__ int   g_Idx[2][BSZ][N][KNB];
__device__ float g_S [2][BSZ][N][N];   // [0]=anchor sigmoid, [1]=raw-pair sigmoid
__device__ __half g_Wh[D * D];         // W0^T as fp16: g_Wh[d*128 + k] = cw0[k*128 + d]

// ---------------- mma.sync / ldmatrix helpers (fp16, m16n8k16) ----------------
__device__ __forceinline__ void mma16(float c[4], const uint32_t a[4],
                                      uint32_t b0, uint32_t b1){
    asm volatile(
        "mma.sync.aligned.m16n8k16.row.col.f32.f16.f16.f32 "
        "{%0,%1,%2,%3}, {%4,%5,%6,%7}, {%8,%9}, {%0,%1,%2,%3};\n"
        : "+f"(c[0]), "+f"(c[1]), "+f"(c[2]), "+f"(c[3])
        : "r"(a[0]), "r"(a[1]), "r"(a[2]), "r"(a[3]), "r"(b0), "r"(b1));
}

__device__ __forceinline__ void ldm4(uint32_t r[4], uint32_t addr){
    asm volatile("ldmatrix.sync.aligned.m8n8.x4.shared.b16 {%0,%1,%2,%3}, [%4];"
        : "=r"(r[0]), "=r"(r[1]), "=r"(r[2]), "=r"(r[3]) : "r"(addr));
}

__device__ __forceinline__ uint32_t ad2(uint32_t a, uint32_t b){
    __half2 ha = *reinterpret_cast<__half2*>(&a);
    __half2 hb = *reinterpret_cast<__half2*>(&b);
    __half2 r  = __habs2(__hsub2(ha, hb));
    return *reinterpret_cast<uint32_t*>(&r);
}

// ---------------- K0: one-time W0^T -> fp16 ----------------
__global__ void prep_w(const float* __restrict__ cw0){
    int e = blockIdx.x * 256 + threadIdx.x;   // 64 blocks x 256 = 16384
    int d = e >> 7, k = e & 127;
    g_Wh[d * D + k] = __float2half_rn(cw0[k * D + d]);
}

// ---------------- K1: P = f @ W0[:D], Q = f @ W0[D:]  (exact fp32) ----------------
__global__ void proj_kernel(const float* __restrict__ f1, const float* __restrict__ f2,
                            const float* __restrict__ sw0){
    __shared__ float fs[4][D];
    int which = blockIdx.x >> 8;
    int grp = blockIdx.x & 255;
    int f = grp >> 7, b = (grp >> 6) & 1, i0 = (grp & 63) * 4;
    const float* featb = (f == 0 ? f1 : f2) + b * N * D;
    int d = threadIdx.x;                      // 128 threads
    for (int e = d; e < 4 * D; e += 128){
        int r = e >> 7, c = e & 127;
        fs[r][c] = featb[(i0 + r) * D + c];
    }
    __syncthreads();
    const float* wb = sw0 + which * D * D + d;
    float a0 = 0.f, a1 = 0.f, a2 = 0.f, a3 = 0.f;
    #pragma unroll 8
    for (int c = 0; c < D; c++){
        float w = wb[c * D];
        a0 = fmaf(fs[0][c], w, a0);
        a1 = fmaf(fs[1][c], w, a1);
        a2 = fmaf(fs[2][c], w, a2);
        a3 = fmaf(fs[3][c], w, a3);
    }
    float* dst = which ? &g_Q[f][b][0][0] : &g_P[f][b][0][0];
    dst[(i0    ) * D + d] = a0;
    dst[(i0 + 1) * D + d] = a1;
    dst[(i0 + 2) * D + d] = a2;
    dst[(i0 + 3) * D + d] = a3;
}

// ---------------- K2: 4 i's per block: sim rows -> top3 -> absorb + indices ----------------
__global__ void topk_kernel(const float* __restrict__ f1, const float* __restrict__ f2,
        const float* __restrict__ sb0, const float* __restrict__ sg,
        const float* __restrict__ sbe, const float* __restrict__ smn,
        const float* __restrict__ sv,  const float* __restrict__ sw1){
    int gb = blockIdx.x;                       // 256 blocks
    int f = gb >> 7, b = (gb >> 6) & 1, i0 = (gb & 63) * 4;
    __shared__ float Ps[4][D], ss[D], tt[D], w1s[D];
    __shared__ float wv[8]; __shared__ int wi[8];
    __shared__ int bidx[4][KNB];
    int t = threadIdx.x, lane = t & 31, warp = t >> 5;
    if (t < D){
        float s = sg[t] * rsqrtf(sv[t] + EPSF);
        ss[t]  = s;
        tt[t]  = (sb0[t] - smn[t]) * s + sbe[t];
        w1s[t] = sw1[t];
        #pragma unroll
        for (int r = 0; r < 4; r++) Ps[r][t] = g_P[f][b][i0 + r][t];
    }
    __syncthreads();
    const float* Qrow = &g_Q[f][b][t][0];
    float simv[4] = {0.f, 0.f, 0.f, 0.f};
    #pragma unroll 4
    for (int d = 0; d < D; d += 4){
        float4 q = *(const float4*)(Qrow + d);
        float s0 = ss[d], s1 = ss[d+1], s2 = ss[d+2], s3 = ss[d+3];
        float t0 = tt[d], t1 = tt[d+1], t2 = tt[d+2], t3 = tt[d+3];
        float w0 = w1s[d], w1 = w1s[d+1], w2 = w1s[d+2], w3 = w1s[d+3];
        #pragma unroll
        for (int r = 0; r < 4; r++){
            float h0 = (Ps[r][d]   + q.x) * s0 + t0;
            float h1 = (Ps[r][d+1] + q.y) * s1 + t1;
            float h2 = (Ps[r][d+2] + q.z) * s2 + t2;
            float h3 = (Ps[r][d+3] + q.w) * s3 + t3;
            simv[r] += fmaxf(h0, 0.f) * w0 + fmaxf(h1, 0.f) * w1
                     + fmaxf(h2, 0.f) * w2 + fmaxf(h3, 0.f) * w3;
        }
    }
    #pragma unroll
    for (int r = 0; r < 4; r++) if (t == i0 + r) simv[r] = NEG_INF;

    for (int r = 0; r < 4; r++){
        for (int k = 0; k < KNB; k++){
            float v = simv[r]; int idx = t;
            #pragma unroll
            for (int off = 16; off; off >>= 1){
                float ov = __shfl_down_sync(0xffffffffu, v, off);
                int   oi = __shfl_down_sync(0xffffffffu, idx, off);
                if (ov > v || (ov == v && oi < idx)){ v = ov; idx = oi; }
            }
            if (lane == 0){ wv[warp] = v; wi[warp] = idx; }
            __syncthreads();
            if (warp == 0){
                float v2 = (lane < 8) ? wv[lane] : NEG_INF;
                int   i2 = (lane < 8) ? wi[lane] : 0x7fffffff;
                #pragma unroll
                for (int off = 4; off; off >>= 1){
                    float ov = __shfl_down_sync(0xffffffffu, v2, off);
                    int   oi = __shfl_down_sync(0xffffffffu, i2, off);
                    if (ov > v2 || (ov == v2 && oi < i2)){ v2 = ov; i2 = oi; }
                }
                if (lane == 0) bidx[r][k] = i2;
            }
            __syncthreads();
            if (t == bidx[r][k]) simv[r] = NEG_INF;
        }
    }
    const float* featb = (f == 0 ? f1 : f2) + b * N * D;
    if (t < D){
        #pragma unroll
        for (int r = 0; r < 4; r++){
            int i = i0 + r;
            int k0 = bidx[r][0], k1 = bidx[r][1], k2 = bidx[r][2];
            float n0 = featb[k0 * D + t], n1 = featb[k1 * D + t], n2 = featb[k2 * D + t];
            g_A[f][b][i][t] = featb[i * D + t] + 0.5f * ((n0 + n1 + n2) * (1.f / 3.f));
        }
    }
    if (t < 4){
        #pragma unroll
        for (int k = 0; k < KNB; k++)
            g_Idx[f][b][i0 + t][k] = bidx[t][k];
    }
}

// ---------------- K3: pair-sigmoid GEMM, 128-pair blocks, 32p x 64d warp tiles ----------------
// XOR-swizzled smem: logical (row, chunk[16B]) -> phys row*256 + (chunk ^ (row&7))*16
#define OFF_PS   0
#define OFF_PT   512
#define OFF_PW   1024
#define OFF_LG   1536     // 128 floats
#define OFF_US   2048     // Ush2: 16 x 68 uint32 = 4352
#define OFF_VS   6400     // Vsh2:  8 x 68 uint32 = 2176
#define OFF_WT   8704     // Wt swizzled fp16 [128 d][128 k] = 32768
#define OFF_XS   41472    // Xs swizzled fp16 [128 pair][128 k] = 32768
#define SMEM_BYTES 74240
#define UPAD 68

__global__ void __launch_bounds__(256, 2) cls_kernel(
    const float* __restrict__ f1,  const float* __restrict__ f2,
    const float* __restrict__ cb0,
    const float* __restrict__ cg,  const float* __restrict__ cbe,
    const float* __restrict__ cm,  const float* __restrict__ cv,
    const float* __restrict__ cw1, const float* __restrict__ cb1)
{
    extern __shared__ char smb[];
    float*    ps    = (float*)   (smb + OFF_PS);
    float*    pt    = (float*)   (smb + OFF_PT);
    float*    pw1   = (float*)   (smb + OFF_PW);
    float*    logit = (float*)   (smb + OFF_LG);
    uint32_t* Ush2  = (uint32_t*)(smb + OFF_US);
    uint32_t* Vsh2  = (uint32_t*)(smb + OFF_VS);
    char*     Xs    = smb + OFF_XS;
    uint32_t smem_base = (uint32_t)__cvta_generic_to_shared(smb);
    uint32_t wt_s = smem_base + OFF_WT;
    uint32_t xs_s = smem_base + OFF_XS;

    int t = threadIdx.x;
    int b = blockIdx.z, i0 = blockIdx.y * 16, j0 = blockIdx.x * 8;
    int lane = t & 31, warp = t >> 5;
    int gid = lane >> 2, tig = lane & 3;
    int pg = warp >> 1, dg = warp & 1;       // 4 pair-groups (32 pairs) x 2 d-groups (64 d)

    // stage swizzled Wt from prepped fp16 (8 x LDG.128/STS.128 per thread)
    #pragma unroll
    for (int i = 0; i < 8; i++){
        int e = t + i * 256;                 // 2048 16B chunks
        int d = e >> 4, ck = e & 15;
        uint4 v = *(const uint4*)(g_Wh + d * D + ck * 8);
        *(uint4*)(smb + OFF_WT + d * 256 + ((ck ^ (d & 7)) << 4)) = v;
    }
    if (t < D){
        float s = cg[t] * rsqrtf(cv[t] + EPSF);
        ps[t]  = s;
        pt[t]  = (cb0[t] - cm[t]) * s + cbe[t];
        pw1[t] = cw1[t];
    }
    float b1v = cb1[0];

    // A (Xs) ldmatrix lane addressing: two m-tiles (16 pairs each)
    int a_row0 = pg * 32 + (lane & 15);
    int a_row1 = a_row0 + 16;
    uint32_t a0_base = xs_s + a_row0 * 256;
    uint32_t a1_base = xs_s + a_row1 * 256;
    int a0_r7 = a_row0 & 7, a_hi = lane >> 4;
    int a1_r7 = a_row1 & 7;
    // B (Wt): row fixed per ng
    int b_row_off = (lane & 7) + (((lane >> 4) & 1) << 3);
    int b_khi = (lane >> 3) & 1;
    uint32_t bw_base[4]; int bw_r7[4];
    #pragma unroll
    for (int ng = 0; ng < 4; ng++){
        int row = dg * 64 + ng * 16 + b_row_off;
        bw_base[ng] = wt_s + row * 256;
        bw_r7[ng]   = row & 7;
    }

    // build mapping: (2 i x 4 j x 16-chunk k) per thread (128 pairs x 16 chunks / 256 thr)
    int g2 = t >> 4, kO = t & 15;
    int ib = (g2 >> 1) * 2;
    int jb = (g2 & 1) * 4;

    #pragma unroll 1
    for (int ch = 0; ch < 2; ch++){
        const float* Ubase = (ch == 0) ? &g_A[0][b][0][0] : (f1 + b * N * D);
        const float* Vbase = (ch == 0) ? &g_A[1][b][0][0] : (f2 + b * N * D);

        __syncthreads();   // prev channel's Xs reads + logit reads complete
        for (int e = t; e < 16 * 64; e += 256){
            int r = e >> 6, c = e & 63;
            float2 fu = *(const float2*)(Ubase + (i0 + r) * D + 2 * c);
            __half2 hu = __floats2half2_rn(fu.x, fu.y);
            Ush2[r * UPAD + c] = *(uint32_t*)&hu;
        }
        for (int e = t; e < 8 * 64; e += 256){
            int r = e >> 6, c = e & 63;
            float2 fv = *(const float2*)(Vbase + (j0 + r) * D + 2 * c);
            __half2 hv = __floats2half2_rn(fv.x, fv.y);
            Vsh2[r * UPAD + c] = *(uint32_t*)&hv;
        }
        if (t < 128) logit[t] = b1v;
        __syncthreads();

        // build X = |U_i - V_j| into swizzled tile: 8 STS.128 per thread
        {
            uint4 u0 = *(const uint4*)(Ush2 +  ib      * UPAD + kO * 4);
            uint4 u1 = *(const uint4*)(Ush2 + (ib + 1) * UPAD + kO * 4);
            #pragma unroll
            for (int jj = 0; jj < 4; jj++){
                uint4 v = *(const uint4*)(Vsh2 + (jb + jj) * UPAD + kO * 4);
                uint4 x0, x1;
                x0.x = ad2(u0.x, v.x); x0.y = ad2(u0.y, v.y);
                x0.z = ad2(u0.z, v.z); x0.w = ad2(u0.w, v.w);
                x1.x = ad2(u1.x, v.x); x1.y = ad2(u1.y, v.y);
                x1.z = ad2(u1.z, v.z); x1.w = ad2(u1.w, v.w);
                int p0 =  ib      * 8 + jb + jj;
                int p1 = (ib + 1) * 8 + jb + jj;
                *(uint4*)(Xs + p0 * 256 + ((kO ^ (p0 & 7)) << 4)) = x0;
                *(uint4*)(Xs + p1 * 256 + ((kO ^ (p1 & 7)) << 4)) = x1;
            }
        }
        __syncthreads();

        float cacc[2][8][4];
        #pragma unroll
        for (int mt = 0; mt < 2; mt++)
            #pragma unroll
            for (int nt = 0; nt < 8; nt++)
                #pragma unroll
                for (int q = 0; q < 4; q++) cacc[mt][nt][q] = 0.f;

        #pragma unroll 1
        for (int ks = 0; ks < 8; ks++){
            int ck = 2 * ks;
            uint32_t aX0[4], aX1[4];
            ldm4(aX0, a0_base + (((ck + a_hi) ^ a0_r7) << 4));
            ldm4(aX1, a1_base + (((ck + a_hi) ^ a1_r7) << 4));
            #pragma unroll
            for (int ng = 0; ng < 4; ng++){
                uint32_t bW[4];
                ldm4(bW, bw_base[ng] + (((ck + b_khi) ^ bw_r7[ng]) << 4));
                mma16(cacc[0][ng * 2],     aX0, bW[0], bW[1]);
                mma16(cacc[0][ng * 2 + 1], aX0, bW[2], bW[3]);
                mma16(cacc[1][ng * 2],     aX1, bW[0], bW[1]);
                mma16(cacc[1][ng * 2 + 1], aX1, bW[2], bW[3]);
            }
        }

        // epilogue: rows = pairs, cols = d (this warp's 64-d half); reduce d in-thread
        #pragma unroll
        for (int mt = 0; mt < 2; mt++){
            float l0 = 0.f, l1 = 0.f;
            #pragma unroll
            for (int nt = 0; nt < 8; nt++){
                int d0 = dg * 64 + (nt >> 1) * 16 + (nt & 1) * 8 + 2 * tig;
                float s0 = ps[d0], t0 = pt[d0], w0 = pw1[d0];
                float s1 = ps[d0 + 1], t1 = pt[d0 + 1], w1 = pw1[d0 + 1];
                float* c = cacc[mt][nt];
                l0 += fmaxf(c[0] * s0 + t0, 0.f) * w0 + fmaxf(c[1] * s1 + t1, 0.f) * w1;
                l1 += fmaxf(c[2] * s0 + t0, 0.f) * w0 + fmaxf(c[3] * s1 + t1, 0.f) * w1;
            }
            l0 += __shfl_xor_sync(0xffffffffu, l0, 1);
            l0 += __shfl_xor_sync(0xffffffffu, l0, 2);
            l1 += __shfl_xor_sync(0xffffffffu, l1, 1);
            l1 += __shfl_xor_sync(0xffffffffu, l1, 2);
            if (tig == 0){
                atomicAdd(&logit[pg * 32 + mt * 16 + gid],     l0);
                atomicAdd(&logit[pg * 32 + mt * 16 + gid + 8], l1);
            }
        }
        __syncthreads();
        if (t < 128){
            float sc = 1.f / (1.f + expf(-logit[t]));
            g_S[ch][b][i0 + (t >> 3)][j0 + (t & 7)] = sc;
        }
    }
}

// ---------------- K4: combine anchor + gathered neighbor scores ----------------
__global__ void combine_kernel(float* __restrict__ out){
    int blk = blockIdx.x;             // 512 = b*256 + i
    int b = blk >> 8, i = blk & 255;
    int j = threadIdx.x;
    __shared__ int ia[KNB];
    if (j < KNB) ia[j] = g_Idx[0][b][i][j];
    __syncthreads();
    float sa = g_S[0][b][i][j];
    const int* bj = &g_Idx[1][b][j][0];
    int b0 = bj[0], b1 = bj[1], b2 = bj[2];
    float s = g_S[1][b][ia[0]][b0] + g_S[1][b][ia[1]][b1] + g_S[1][b][ia[2]][b2];
    out[(b * N + i) * N + j] = 0.5f * sa + (1.f / 6.f) * s;
}

// ---------------- launch ----------------
extern "C" void kernel_launch(void* const* d_in, const int* in_sizes, int n_in,
                              void* d_out, int out_size){
    const float* f1  = (const float*)d_in[0];
    const float* f2  = (const float*)d_in[1];
    const float* sw0 = (const float*)d_in[2];
    const float* sb0 = (const float*)d_in[3];
    const float* sg  = (const float*)d_in[4];
    const float* sbe = (const float*)d_in[5];
    const float* smn = (const float*)d_in[6];
    const float* sv  = (const float*)d_in[7];
    const float* sw1 = (const float*)d_in[8];
    /* d_in[9] = sim_b1: rank-invariant, unused */
    const float* cw0 = (const float*)d_in[10];
    const float* cb0 = (const float*)d_in[11];
    const float* cg  = (const float*)d_in[12];
    const float* cbe = (const float*)d_in[13];
    const float* cm  = (const float*)d_in[14];
    const float* cv  = (const float*)d_in[15];
    const float* cw1 = (const float*)d_in[16];
    const float* cb1 = (const float*)d_in[17];
    float* out = (float*)d_out;

    cudaFuncSetAttribute(cls_kernel, cudaFuncAttributeMaxDynamicSharedMemorySize,
                         SMEM_BYTES);

    prep_w<<<64, 256>>>(cw0);
    proj_kernel<<<512, 128>>>(f1, f2, sw0);
    topk_kernel<<<256, 256>>>(f1, f2, sb0, sg, sbe, smn, sv, sw1);
    dim3 grid(32, 16, 2);
    cls_kernel<<<grid, 256, SMEM_BYTES>>>(
        f1, f2, cb0, cg, cbe, cm, cv, cw1, cb1);
    combine_kernel<<<512, 256>>>(out);
}